// round 1
// baseline (speedup 1.0000x reference)
#include <cuda_runtime.h>
#include <math.h>

#define NB   32768
#define IND  336
#define HD   256
#define NE   16
#define NACT 64

// ---------------- device scratch (no allocations allowed) ----------------
__device__ float g_inp[(size_t)NB * IND];       // staged input rows [B,336]
__device__ float g_cskip[NB];
__device__ float g_cout[NB];
__device__ int   g_count[NE];
__device__ float g_entropy;
__device__ int   g_bucket[NE * NB];             // packed row | slot<<16
__device__ float g_bw[NE * NB];                 // normalized gate weight
__device__ float g_eout[(size_t)NB * 4 * HD];   // per-(row,slot) weighted expert out

__device__ __forceinline__ float mishf(float v) {
    float sp = (v > 20.f) ? v : log1pf(expf(v));
    return v * tanhf(sp);
}

// ---------------- shared 64x256 fp32 GEMM accumulator ----------------
// Block: 256 threads. warp = ty (0..7) owns rows ty*8..ty*8+7; lane = tx (0..31)
// owns cols tx*4..tx*4+3 and 128+tx*4..+3. A is m-major in smem (broadcast
// scalar a-loads, conflict-free float4 b-loads from the streamed W tile).
template<int LDA>
__device__ __forceinline__ void gemm64x256(
    const float* __restrict__ A, int K,
    const float* __restrict__ Wg, float* __restrict__ Ws,
    float (&acc)[8][8], int ty, int tx, int tid)
{
#pragma unroll
    for (int mi = 0; mi < 8; mi++)
#pragma unroll
        for (int ni = 0; ni < 8; ni++) acc[mi][ni] = 0.f;

    const float* Abase = A + ty * 8 * LDA;
    for (int kt = 0; kt < K; kt += 32) {
        int kc = min(32, K - kt);
        __syncthreads();
#pragma unroll
        for (int i = 0; i < 8; i++) {
            int f4 = i * 256 + tid;
            int r  = f4 >> 6;
            int c  = (f4 & 63) << 2;
            if (r < kc)
                *(float4*)&Ws[r * 256 + c] = *(const float4*)&Wg[(size_t)(kt + r) * 256 + c];
        }
        __syncthreads();
        const float* Ap = Abase + kt;
        if (kc == 32) {
#pragma unroll 2
            for (int k = 0; k < 32; k++) {
                float a[8];
#pragma unroll
                for (int mi = 0; mi < 8; mi++) a[mi] = Ap[mi * LDA + k];
                float4 b0 = *(const float4*)&Ws[k * 256 + (tx << 2)];
                float4 b1 = *(const float4*)&Ws[k * 256 + 128 + (tx << 2)];
#pragma unroll
                for (int mi = 0; mi < 8; mi++) {
                    acc[mi][0] = fmaf(a[mi], b0.x, acc[mi][0]);
                    acc[mi][1] = fmaf(a[mi], b0.y, acc[mi][1]);
                    acc[mi][2] = fmaf(a[mi], b0.z, acc[mi][2]);
                    acc[mi][3] = fmaf(a[mi], b0.w, acc[mi][3]);
                    acc[mi][4] = fmaf(a[mi], b1.x, acc[mi][4]);
                    acc[mi][5] = fmaf(a[mi], b1.y, acc[mi][5]);
                    acc[mi][6] = fmaf(a[mi], b1.z, acc[mi][6]);
                    acc[mi][7] = fmaf(a[mi], b1.w, acc[mi][7]);
                }
            }
        } else {
            for (int k = 0; k < kc; k++) {
                float a[8];
#pragma unroll
                for (int mi = 0; mi < 8; mi++) a[mi] = Ap[mi * LDA + k];
                float4 b0 = *(const float4*)&Ws[k * 256 + (tx << 2)];
                float4 b1 = *(const float4*)&Ws[k * 256 + 128 + (tx << 2)];
#pragma unroll
                for (int mi = 0; mi < 8; mi++) {
                    acc[mi][0] = fmaf(a[mi], b0.x, acc[mi][0]);
                    acc[mi][1] = fmaf(a[mi], b0.y, acc[mi][1]);
                    acc[mi][2] = fmaf(a[mi], b0.z, acc[mi][2]);
                    acc[mi][3] = fmaf(a[mi], b0.w, acc[mi][3]);
                    acc[mi][4] = fmaf(a[mi], b1.x, acc[mi][4]);
                    acc[mi][5] = fmaf(a[mi], b1.y, acc[mi][5]);
                    acc[mi][6] = fmaf(a[mi], b1.z, acc[mi][6]);
                    acc[mi][7] = fmaf(a[mi], b1.w, acc[mi][7]);
                }
            }
        }
    }
}

// mode 0: mish, mode 1: relu
__device__ __forceinline__ void store_act(
    float (&acc)[8][8], const float* __restrict__ bias,
    float* __restrict__ Out, int ldo, int ty, int tx, int mode)
{
#pragma unroll
    for (int mi = 0; mi < 8; mi++) {
        float* o = Out + (ty * 8 + mi) * ldo;
        float4 v0, v1;
        float n0 = acc[mi][0] + __ldg(&bias[(tx << 2) + 0]);
        float n1 = acc[mi][1] + __ldg(&bias[(tx << 2) + 1]);
        float n2 = acc[mi][2] + __ldg(&bias[(tx << 2) + 2]);
        float n3 = acc[mi][3] + __ldg(&bias[(tx << 2) + 3]);
        float n4 = acc[mi][4] + __ldg(&bias[128 + (tx << 2) + 0]);
        float n5 = acc[mi][5] + __ldg(&bias[128 + (tx << 2) + 1]);
        float n6 = acc[mi][6] + __ldg(&bias[128 + (tx << 2) + 2]);
        float n7 = acc[mi][7] + __ldg(&bias[128 + (tx << 2) + 3]);
        if (mode == 0) {
            v0.x = mishf(n0); v0.y = mishf(n1); v0.z = mishf(n2); v0.w = mishf(n3);
            v1.x = mishf(n4); v1.y = mishf(n5); v1.z = mishf(n6); v1.w = mishf(n7);
        } else {
            v0.x = fmaxf(n0, 0.f); v0.y = fmaxf(n1, 0.f); v0.z = fmaxf(n2, 0.f); v0.w = fmaxf(n3, 0.f);
            v1.x = fmaxf(n4, 0.f); v1.y = fmaxf(n5, 0.f); v1.z = fmaxf(n6, 0.f); v1.w = fmaxf(n7, 0.f);
        }
        *(float4*)&o[(tx << 2)]        = v0;
        *(float4*)&o[128 + (tx << 2)] = v1;
    }
}

// ---------------- kernel 1: per-row prep (scalings + time MLP) ----------------
__global__ void prep_kernel(
    const float* __restrict__ x, const float* __restrict__ sigma,
    const float* __restrict__ state,
    const float* __restrict__ tW1, const float* __restrict__ tb1,
    const float* __restrict__ tW2, const float* __restrict__ tb2)
{
    if (blockIdx.x == 0 && threadIdx.x < NE) g_count[threadIdx.x] = 0;
    if (blockIdx.x == 0 && threadIdx.x == NE) g_entropy = 0.f;

    int wid  = (blockIdx.x * blockDim.x + threadIdx.x) >> 5;
    int lane = threadIdx.x & 31;
    if (wid >= NB) return;
    int r = wid;

    float sg  = __ldg(&sigma[r]);
    float sd2 = 0.25f;
    float d   = sg - 0.002f;
    float cskip = sd2 / (d * d + sd2);
    float inv = rsqrtf(sg * sg + sd2);
    float cout = d * 0.5f * inv;
    float cin  = inv;
    float rt   = 250.0f * logf(sg + 1e-44f);

    float pe[16];
#pragma unroll
    for (int i = 0; i < 8; i++) {
        float fr = expf((-9.210340371976184f / 7.0f) * (float)i);
        float s, c;
        sincosf(rt * fr, &s, &c);
        pe[i] = s; pe[i + 8] = c;
    }
    // layer1: 16 -> 32, lane j computes h1[j]
    float h1 = __ldg(&tb1[lane]);
#pragma unroll
    for (int i = 0; i < 16; i++) h1 = fmaf(pe[i], __ldg(&tW1[i * 32 + lane]), h1);
    h1 = mishf(h1);
    // layer2: 32 -> 16
    float tacc = (lane < 16) ? __ldg(&tb2[lane]) : 0.f;
#pragma unroll
    for (int j = 0; j < 32; j++) {
        float hj = __shfl_sync(0xffffffffu, h1, j);
        if (lane < 16) tacc = fmaf(hj, __ldg(&tW2[j * 16 + lane]), tacc);
    }
    float* row = g_inp + (size_t)r * IND;
    row[lane]      = cin * __ldg(&x[r * 64 + lane]);
    row[32 + lane] = cin * __ldg(&x[r * 64 + 32 + lane]);
    if (lane < 16) row[64 + lane] = tacc;
#pragma unroll
    for (int i = 0; i < 8; i++)
        row[80 + lane + i * 32] = __ldg(&state[r * 256 + lane + i * 32]);
    if (lane == 0) { g_cskip[r] = cskip; g_cout[r] = cout; }
}

// ---------------- kernel 2: gate + softmax + top4 + routing ----------------
__global__ void __launch_bounds__(256, 1) gate_kernel(
    const float* __restrict__ gW1, const float* __restrict__ gb1,
    const float* __restrict__ gW2, const float* __restrict__ gb2)
{
    extern __shared__ float smem[];
    float* Xs   = smem;                  // 64*340
    float* G1   = Xs + 64 * 340;         // 64*260
    float* Ws   = G1 + 64 * 260;         // 32*256
    float* W2s  = Ws + 32 * 256;         // 256*16
    float* entA = W2s + 256 * 16;        // 1

    int tid = threadIdx.x, ty = tid >> 5, tx = tid & 31;
    int base = blockIdx.x * 64;
    if (tid == 0) *entA = 0.f;
    for (int i = tid; i < 4096; i += 256) W2s[i] = gW2[i];
#pragma unroll
    for (int rr = 0; rr < 8; rr++) {
        int m = ty * 8 + rr;
        const float* src = g_inp + (size_t)(base + m) * IND;
        for (int k = tx; k < IND; k += 32) Xs[m * 340 + k] = src[k];
    }
    float acc[8][8];
    gemm64x256<340>(Xs, IND, gW1, Ws, acc, ty, tx, tid);
    store_act(acc, gb1, G1, 260, ty, tx, /*relu*/1);
    __syncthreads();

    // layer2: 256 -> 16, per-warp per-row
    int j = tx & 15, kh = tx >> 4;
    for (int rr = 0; rr < 8; rr++) {
        int m = ty * 8 + rr;
        int row = base + m;
        const float* g1 = &G1[m * 260];
        float s = 0.f;
        int k0 = kh * 128;
#pragma unroll 4
        for (int k = 0; k < 128; k++) s = fmaf(g1[k0 + k], W2s[(k0 + k) * 16 + j], s);
        s += __shfl_down_sync(0xffffffffu, s, 16);
        float gv = s + __ldg(&gb2[j]);
        float p[16];
#pragma unroll
        for (int q = 0; q < 16; q++) p[q] = __shfl_sync(0xffffffffu, gv, q);
        float mx = p[0];
#pragma unroll
        for (int q = 1; q < 16; q++) mx = fmaxf(mx, p[q]);
        float Z = 0.f;
#pragma unroll
        for (int q = 0; q < 16; q++) { p[q] = expf(p[q] - mx); Z += p[q]; }
        float invZ = 1.f / Z;
        float ent = 0.f;
#pragma unroll
        for (int q = 0; q < 16; q++) { p[q] *= invZ; ent -= p[q] * logf(p[q] + 1e-9f); }
        // top-4 (strict >, first index wins ties — matches jax.lax.top_k)
        unsigned usedm = 0;
        int   idx[4]; float val[4]; float wsum = 0.f;
#pragma unroll
        for (int s4 = 0; s4 < 4; s4++) {
            int best = 0; float bv = -1.f;
#pragma unroll
            for (int q = 0; q < 16; q++) {
                bool free = !((usedm >> q) & 1u);
                if (free && p[q] > bv) { bv = p[q]; best = q; }
            }
            usedm |= (1u << best);
            idx[s4] = best; val[s4] = bv; wsum += bv;
        }
        float invw = 1.f / (wsum + 1e-9f);
        if (tx < 4) {
            int ee = idx[tx];
            int pos = atomicAdd(&g_count[ee], 1);
            g_bucket[ee * NB + pos] = row | (tx << 16);
            g_bw[ee * NB + pos] = val[tx] * invw;
        }
        if (tx == 0) atomicAdd(entA, ent);
    }
    __syncthreads();
    if (tid == 0) atomicAdd(&g_entropy, *entA);
}

// ---------------- kernel 3: routed fused 3-layer expert MLP ----------------
__global__ void __launch_bounds__(256, 1) expert_kernel(
    const float* __restrict__ eW1, const float* __restrict__ eb1,
    const float* __restrict__ eW2, const float* __restrict__ eb2,
    const float* __restrict__ eW3, const float* __restrict__ eb3)
{
    extern __shared__ float smem[];
    int e = blockIdx.y;
    int cnt = g_count[e];
    int base = blockIdx.x * 64;
    if (base >= cnt) return;

    float* Xs   = smem;                   // 64*340 (also reused as L2 output, ld 260)
    float* Bs   = Xs + 64 * 340;          // 64*260
    float* Ws   = Bs + 64 * 260;          // 32*256
    float* swt  = Ws + 32 * 256;          // 64
    int*   srow = (int*)(swt + 64);       // 64

    int tid = threadIdx.x, ty = tid >> 5, tx = tid & 31;
    if (tid < 64) {
        int gi = base + tid;
        int gj = (gi < cnt) ? gi : (cnt - 1);
        srow[tid] = g_bucket[e * NB + gj];
        swt[tid]  = (gi < cnt) ? g_bw[e * NB + gj] : 0.f;
    }
    __syncthreads();
#pragma unroll
    for (int rr = 0; rr < 8; rr++) {
        int m = ty * 8 + rr;
        int rid = srow[m] & 0xFFFF;
        const float* src = g_inp + (size_t)rid * IND;
        for (int k = tx; k < IND; k += 32) Xs[m * 340 + k] = src[k];
    }

    float acc[8][8];
    gemm64x256<340>(Xs, IND, eW1 + (size_t)e * IND * HD, Ws, acc, ty, tx, tid);
    store_act(acc, eb1 + e * HD, Bs, 260, ty, tx, 0);

    gemm64x256<260>(Bs, HD, eW2 + (size_t)e * HD * HD, Ws, acc, ty, tx, tid);
    store_act(acc, eb2 + e * HD, Xs, 260, ty, tx, 0);   // reuse Xs, ld=260

    gemm64x256<260>(Xs, HD, eW3 + (size_t)e * HD * HD, Ws, acc, ty, tx, tid);

    const float* b3 = eb3 + e * HD;
#pragma unroll
    for (int mi = 0; mi < 8; mi++) {
        int m = ty * 8 + mi;
        int gi = base + m;
        if (gi < cnt) {
            int packed = srow[m];
            int row = packed & 0xFFFF;
            int slot = packed >> 16;
            float w = swt[m];
            float* dst = g_eout + ((size_t)(row * 4 + slot)) * HD;
            float4 v0, v1;
            v0.x = w * mishf(acc[mi][0] + __ldg(&b3[(tx << 2) + 0]));
            v0.y = w * mishf(acc[mi][1] + __ldg(&b3[(tx << 2) + 1]));
            v0.z = w * mishf(acc[mi][2] + __ldg(&b3[(tx << 2) + 2]));
            v0.w = w * mishf(acc[mi][3] + __ldg(&b3[(tx << 2) + 3]));
            v1.x = w * mishf(acc[mi][4] + __ldg(&b3[128 + (tx << 2) + 0]));
            v1.y = w * mishf(acc[mi][5] + __ldg(&b3[128 + (tx << 2) + 1]));
            v1.z = w * mishf(acc[mi][6] + __ldg(&b3[128 + (tx << 2) + 2]));
            v1.w = w * mishf(acc[mi][7] + __ldg(&b3[128 + (tx << 2) + 3]));
            *(float4*)&dst[(tx << 2)]        = v0;
            *(float4*)&dst[128 + (tx << 2)] = v1;
        }
    }
}

// ---------------- kernel 4: combine slots + final linear + epilogue ----------------
__global__ void __launch_bounds__(256, 1) final_kernel(
    const float* __restrict__ x, const float* __restrict__ fW,
    const float* __restrict__ fb, float* __restrict__ out)
{
    extern __shared__ float smem[];
    float* cs  = smem;             // 64*260
    float* fWs = cs + 64 * 260;    // 256*64
    int tid = threadIdx.x;
    int base = blockIdx.x * 64;

    for (int i = tid; i < 4096; i += 256)
        ((float4*)fWs)[i] = ((const float4*)fW)[i];
    for (int idx = tid; idx < 64 * 256; idx += 256) {
        int m = idx >> 8, n = idx & 255;
        size_t rb = ((size_t)(base + m)) * 4 * HD + n;
        float v = g_eout[rb] + g_eout[rb + 256] + g_eout[rb + 512] + g_eout[rb + 768];
        cs[m * 260 + n] = v;
    }
    __syncthreads();

    int ty = tid >> 4, tx = tid & 15;
    float acc[4][4];
#pragma unroll
    for (int mi = 0; mi < 4; mi++)
#pragma unroll
        for (int ci = 0; ci < 4; ci++) acc[mi][ci] = 0.f;
#pragma unroll 4
    for (int k = 0; k < 256; k++) {
        float4 b = *(const float4*)&fWs[k * 64 + (tx << 2)];
#pragma unroll
        for (int mi = 0; mi < 4; mi++) {
            float a = cs[(ty * 4 + mi) * 260 + k];
            acc[mi][0] = fmaf(a, b.x, acc[mi][0]);
            acc[mi][1] = fmaf(a, b.y, acc[mi][1]);
            acc[mi][2] = fmaf(a, b.z, acc[mi][2]);
            acc[mi][3] = fmaf(a, b.w, acc[mi][3]);
        }
    }
#pragma unroll
    for (int mi = 0; mi < 4; mi++) {
        int row = base + ty * 4 + mi;
        float co = g_cout[row], ck = g_cskip[row];
        float4 xr = *(const float4*)&x[row * 64 + (tx << 2)];
        float4 o;
        o.x = fminf(fmaxf(co * (acc[mi][0] + __ldg(&fb[(tx << 2) + 0])) + ck * xr.x, -1.f), 1.f);
        o.y = fminf(fmaxf(co * (acc[mi][1] + __ldg(&fb[(tx << 2) + 1])) + ck * xr.y, -1.f), 1.f);
        o.z = fminf(fmaxf(co * (acc[mi][2] + __ldg(&fb[(tx << 2) + 2])) + ck * xr.z, -1.f), 1.f);
        o.w = fminf(fmaxf(co * (acc[mi][3] + __ldg(&fb[(tx << 2) + 3])) + ck * xr.w, -1.f), 1.f);
        *(float4*)&out[row * 64 + (tx << 2)] = o;
    }
}

// ---------------- kernel 5: aux loss ----------------
__global__ void aux_kernel(float* __restrict__ out, int out_size)
{
    if (threadIdx.x == 0 && out_size > NB * NACT) {
        float load[NE], mean = 0.f;
#pragma unroll
        for (int e = 0; e < NE; e++) { load[e] = (float)g_count[e] / (32768.0f + 1e-9f); mean += load[e]; }
        mean *= (1.0f / NE);
        float var = 0.f;
#pragma unroll
        for (int e = 0; e < NE; e++) { float d = load[e] - mean; var += d * d; }
        var *= (1.0f / (NE - 1));
        out[NB * NACT] = var + g_entropy / 32768.0f;
    }
}

extern "C" void kernel_launch(void* const* d_in, const int* in_sizes, int n_in,
                              void* d_out, int out_size)
{
    const float* x     = (const float*)d_in[0];
    const float* sigma = (const float*)d_in[1];
    const float* state = (const float*)d_in[2];
    const float* tW1 = (const float*)d_in[3];
    const float* tb1 = (const float*)d_in[4];
    const float* tW2 = (const float*)d_in[5];
    const float* tb2 = (const float*)d_in[6];
    const float* gW1 = (const float*)d_in[7];
    const float* gb1 = (const float*)d_in[8];
    const float* gW2 = (const float*)d_in[9];
    const float* gb2 = (const float*)d_in[10];
    const float* eW1 = (const float*)d_in[11];
    const float* eb1 = (const float*)d_in[12];
    const float* eW2 = (const float*)d_in[13];
    const float* eb2 = (const float*)d_in[14];
    const float* eW3 = (const float*)d_in[15];
    const float* eb3 = (const float*)d_in[16];
    const float* fW  = (const float*)d_in[17];
    const float* fb  = (const float*)d_in[18];
    float* out = (float*)d_out;

    const int gateSmem = (64 * 340 + 64 * 260 + 32 * 256 + 256 * 16 + 16) * 4;
    const int expSmem  = (64 * 340 + 64 * 260 + 32 * 256 + 64 + 64 + 16) * 4;
    const int finSmem  = (64 * 260 + 256 * 64 + 16) * 4;
    cudaFuncSetAttribute(gate_kernel,   cudaFuncAttributeMaxDynamicSharedMemorySize, gateSmem);
    cudaFuncSetAttribute(expert_kernel, cudaFuncAttributeMaxDynamicSharedMemorySize, expSmem);
    cudaFuncSetAttribute(final_kernel,  cudaFuncAttributeMaxDynamicSharedMemorySize, finSmem);

    prep_kernel<<<NB / 8, 256>>>(x, sigma, state, tW1, tb1, tW2, tb2);
    gate_kernel<<<NB / 64, 256, gateSmem>>>(gW1, gb1, gW2, gb2);
    expert_kernel<<<dim3(NB / 64, NE), 256, expSmem>>>(eW1, eb1, eW2, eb2, eW3, eb3);
    final_kernel<<<NB / 64, 256, finSmem>>>(x, fW, fb, out);
    aux_kernel<<<1, 32>>>(out, out_size);
}

// round 2
// speedup vs baseline: 1.0631x; 1.0631x over previous
#include <cuda_runtime.h>
#include <math.h>

#define NB   32768
#define IND  336
#define HD   256
#define NE   16
#define NACT 64

// ---------------- device scratch (no allocations allowed) ----------------
__device__ float g_inp[(size_t)NB * IND];       // staged input rows [B,336]
__device__ float g_cskip[NB];
__device__ float g_cout[NB];
__device__ int   g_count[NE];
__device__ float g_entropy;
__device__ int   g_bucket[NE * NB];             // packed row | slot<<16
__device__ float g_bw[NE * NB];                 // normalized gate weight
__device__ float g_eout[(size_t)NB * 4 * HD];   // per-(row,slot) weighted expert out

__device__ __forceinline__ float mishf(float v) {
    float sp = (v > 20.f) ? v : log1pf(expf(v));
    return v * tanhf(sp);
}

// packed fp32x2 FMA (sm_103a FFMA2 — 2x fp32 throughput vs FFMA-3reg)
#define FMA2(d, a, b) asm("fma.rn.f32x2 %0, %1, %2, %0;" : "+l"(d) : "l"(a), "l"(b))

__device__ __forceinline__ unsigned long long dup2(float v) {
    unsigned long long r;
    asm("mov.b64 %0, {%1, %1};" : "=l"(r) : "r"(__float_as_uint(v)));
    return r;
}
__device__ __forceinline__ float2 unpack2(unsigned long long v) {
    float2 r;
    asm("mov.b64 {%0, %1}, %2;" : "=f"(r.x), "=f"(r.y) : "l"(v));
    return r;
}

// ---------------- shared 64x256 packed-fp32 GEMM ----------------
// Block: 256 threads. warp ty (0..7) owns rows ty*8..+7; lane tx owns cols
// tx*4..+3 and 128+tx*4..+3, held as f32x2 pairs. W tile double-buffered
// (Ws0/Ws1, 32x256 each); global loads of tile t+1 overlap compute of tile t.
template<int LDA>
__device__ __forceinline__ void gemm64x256p(
    const float* __restrict__ A, int K,
    const float* __restrict__ Wg, float* __restrict__ Ws0, float* __restrict__ Ws1,
    unsigned long long (&acc)[8][4], int ty, int tx, int tid)
{
#pragma unroll
    for (int mi = 0; mi < 8; mi++)
#pragma unroll
        for (int ni = 0; ni < 4; ni++) acc[mi][ni] = 0ull;

    const float* Abase = A + ty * 8 * LDA;
    const int ntiles = (K + 31) >> 5;
    const int tx4 = tx << 2;

    float4 pf[8];
    int pr[8], pc[8];
#pragma unroll
    for (int i = 0; i < 8; i++) {
        int f4 = i * 256 + tid;
        pr[i] = f4 >> 6;
        pc[i] = (f4 & 63) << 2;
    }
    // prefetch tile 0
#pragma unroll
    for (int i = 0; i < 8; i++) {
        int k = pr[i];
        pf[i] = (k < K) ? *(const float4*)&Wg[(size_t)k * 256 + pc[i]]
                        : make_float4(0.f, 0.f, 0.f, 0.f);
    }
    __syncthreads();   // protect Ws buffers / A staging from prior phase

    for (int t = 0; t < ntiles; t++) {
        float* Ws = (t & 1) ? Ws1 : Ws0;
#pragma unroll
        for (int i = 0; i < 8; i++)
            *(float4*)&Ws[pr[i] * 256 + pc[i]] = pf[i];
        // prefetch next tile (overlaps compute below)
        if (t + 1 < ntiles) {
            int kt = (t + 1) << 5;
#pragma unroll
            for (int i = 0; i < 8; i++) {
                int k = kt + pr[i];
                pf[i] = (k < K) ? *(const float4*)&Wg[(size_t)k * 256 + pc[i]]
                                : make_float4(0.f, 0.f, 0.f, 0.f);
            }
        }
        __syncthreads();
        int kt = t << 5;
        int kc = min(32, K - kt);           // 32 or 16 (always even)
        const float* Ap = Abase + kt;
        for (int k = 0; k < kc; k += 2) {
            float2 a01[8];
#pragma unroll
            for (int mi = 0; mi < 8; mi++)
                a01[mi] = *(const float2*)&Ap[mi * LDA + k];
#pragma unroll
            for (int kk = 0; kk < 2; kk++) {
                const float* wrow = &Ws[(k + kk) * 256];
                ulonglong2 bb0 = *(const ulonglong2*)&wrow[tx4];
                ulonglong2 bb1 = *(const ulonglong2*)&wrow[128 + tx4];
#pragma unroll
                for (int mi = 0; mi < 8; mi++) {
                    unsigned long long a2 = dup2(kk ? a01[mi].y : a01[mi].x);
                    FMA2(acc[mi][0], a2, bb0.x);
                    FMA2(acc[mi][1], a2, bb0.y);
                    FMA2(acc[mi][2], a2, bb1.x);
                    FMA2(acc[mi][3], a2, bb1.y);
                }
            }
        }
        __syncthreads();
    }
}

// mode 0: mish, mode 1: relu
__device__ __forceinline__ void store_act_p(
    unsigned long long (&acc)[8][4], const float* __restrict__ bias,
    float* __restrict__ Out, int ldo, int ty, int tx, int mode)
{
    const int tx4 = tx << 2;
    float bs[8];
#pragma unroll
    for (int i = 0; i < 4; i++) { bs[i] = __ldg(&bias[tx4 + i]); bs[4 + i] = __ldg(&bias[128 + tx4 + i]); }
#pragma unroll
    for (int mi = 0; mi < 8; mi++) {
        float* o = Out + (ty * 8 + mi) * ldo;
        float2 p0 = unpack2(acc[mi][0]);
        float2 p1 = unpack2(acc[mi][1]);
        float2 p2 = unpack2(acc[mi][2]);
        float2 p3 = unpack2(acc[mi][3]);
        float n[8] = { p0.x + bs[0], p0.y + bs[1], p1.x + bs[2], p1.y + bs[3],
                       p2.x + bs[4], p2.y + bs[5], p3.x + bs[6], p3.y + bs[7] };
        float4 v0, v1;
        if (mode == 0) {
            v0.x = mishf(n[0]); v0.y = mishf(n[1]); v0.z = mishf(n[2]); v0.w = mishf(n[3]);
            v1.x = mishf(n[4]); v1.y = mishf(n[5]); v1.z = mishf(n[6]); v1.w = mishf(n[7]);
        } else {
            v0.x = fmaxf(n[0], 0.f); v0.y = fmaxf(n[1], 0.f); v0.z = fmaxf(n[2], 0.f); v0.w = fmaxf(n[3], 0.f);
            v1.x = fmaxf(n[4], 0.f); v1.y = fmaxf(n[5], 0.f); v1.z = fmaxf(n[6], 0.f); v1.w = fmaxf(n[7], 0.f);
        }
        *(float4*)&o[tx4]       = v0;
        *(float4*)&o[128 + tx4] = v1;
    }
}

// ---------------- kernel 1: per-row prep (scalings + time MLP) ----------------
__global__ void prep_kernel(
    const float* __restrict__ x, const float* __restrict__ sigma,
    const float* __restrict__ state,
    const float* __restrict__ tW1, const float* __restrict__ tb1,
    const float* __restrict__ tW2, const float* __restrict__ tb2)
{
    if (blockIdx.x == 0 && threadIdx.x < NE) g_count[threadIdx.x] = 0;
    if (blockIdx.x == 0 && threadIdx.x == NE) g_entropy = 0.f;

    int wid  = (blockIdx.x * blockDim.x + threadIdx.x) >> 5;
    int lane = threadIdx.x & 31;
    if (wid >= NB) return;
    int r = wid;

    float sg  = __ldg(&sigma[r]);
    float sd2 = 0.25f;
    float d   = sg - 0.002f;
    float cskip = sd2 / (d * d + sd2);
    float inv = rsqrtf(sg * sg + sd2);
    float cout = d * 0.5f * inv;
    float cin  = inv;
    float rt   = 250.0f * logf(sg + 1e-44f);

    float pe[16];
#pragma unroll
    for (int i = 0; i < 8; i++) {
        float fr = expf((-9.210340371976184f / 7.0f) * (float)i);
        float s, c;
        sincosf(rt * fr, &s, &c);
        pe[i] = s; pe[i + 8] = c;
    }
    float h1 = __ldg(&tb1[lane]);
#pragma unroll
    for (int i = 0; i < 16; i++) h1 = fmaf(pe[i], __ldg(&tW1[i * 32 + lane]), h1);
    h1 = mishf(h1);
    float tacc = (lane < 16) ? __ldg(&tb2[lane]) : 0.f;
#pragma unroll
    for (int j = 0; j < 32; j++) {
        float hj = __shfl_sync(0xffffffffu, h1, j);
        if (lane < 16) tacc = fmaf(hj, __ldg(&tW2[j * 16 + lane]), tacc);
    }
    float* row = g_inp + (size_t)r * IND;
    row[lane]      = cin * __ldg(&x[r * 64 + lane]);
    row[32 + lane] = cin * __ldg(&x[r * 64 + 32 + lane]);
    if (lane < 16) row[64 + lane] = tacc;
#pragma unroll
    for (int i = 0; i < 8; i++)
        row[80 + lane + i * 32] = __ldg(&state[r * 256 + lane + i * 32]);
    if (lane == 0) { g_cskip[r] = cskip; g_cout[r] = cout; }
}

// ---------------- kernel 2: gate + softmax + top4 + routing ----------------
__global__ void __launch_bounds__(256, 1) gate_kernel(
    const float* __restrict__ gW1, const float* __restrict__ gb1,
    const float* __restrict__ gW2, const float* __restrict__ gb2)
{
    extern __shared__ float smem[];
    float* Xs   = smem;                  // 64*340
    float* G1   = Xs + 64 * 340;         // 64*260
    float* Ws0  = G1 + 64 * 260;         // 32*256 (after gemm1, front 4096 reused as W2s)
    float* Ws1  = Ws0 + 32 * 256;        // 32*256
    float* entA = Ws1 + 32 * 256;        // 1

    int tid = threadIdx.x, ty = tid >> 5, tx = tid & 31;
    int base = blockIdx.x * 64;
    if (tid == 0) *entA = 0.f;
#pragma unroll
    for (int rr = 0; rr < 8; rr++) {
        int m = ty * 8 + rr;
        const float* src = g_inp + (size_t)(base + m) * IND;
        for (int k = tx; k < IND; k += 32) Xs[m * 340 + k] = src[k];
    }
    unsigned long long acc[8][4];
    gemm64x256p<340>(Xs, IND, gW1, Ws0, Ws1, acc, ty, tx, tid);
    store_act_p(acc, gb1, G1, 260, ty, tx, /*relu*/1);
    __syncthreads();

    float* W2s = Ws0;
    for (int i = tid; i < 4096; i += 256) W2s[i] = gW2[i];
    __syncthreads();

    // layer2: 256 -> 16, per-warp per-row
    int j = tx & 15, kh = tx >> 4;
    for (int rr = 0; rr < 8; rr++) {
        int m = ty * 8 + rr;
        int row = base + m;
        const float* g1 = &G1[m * 260];
        float s = 0.f;
        int k0 = kh * 128;
#pragma unroll 4
        for (int k = 0; k < 128; k++) s = fmaf(g1[k0 + k], W2s[(k0 + k) * 16 + j], s);
        s += __shfl_down_sync(0xffffffffu, s, 16);
        float gv = s + __ldg(&gb2[j]);
        float p[16];
#pragma unroll
        for (int q = 0; q < 16; q++) p[q] = __shfl_sync(0xffffffffu, gv, q);
        float mx = p[0];
#pragma unroll
        for (int q = 1; q < 16; q++) mx = fmaxf(mx, p[q]);
        float Z = 0.f;
#pragma unroll
        for (int q = 0; q < 16; q++) { p[q] = expf(p[q] - mx); Z += p[q]; }
        float invZ = 1.f / Z;
        float ent = 0.f;
#pragma unroll
        for (int q = 0; q < 16; q++) { p[q] *= invZ; ent -= p[q] * logf(p[q] + 1e-9f); }
        unsigned usedm = 0;
        int   idx[4]; float val[4]; float wsum = 0.f;
#pragma unroll
        for (int s4 = 0; s4 < 4; s4++) {
            int best = 0; float bv = -1.f;
#pragma unroll
            for (int q = 0; q < 16; q++) {
                bool free = !((usedm >> q) & 1u);
                if (free && p[q] > bv) { bv = p[q]; best = q; }
            }
            usedm |= (1u << best);
            idx[s4] = best; val[s4] = bv; wsum += bv;
        }
        float invw = 1.f / (wsum + 1e-9f);
        if (tx < 4) {
            int ee = idx[tx];
            int pos = atomicAdd(&g_count[ee], 1);
            g_bucket[ee * NB + pos] = row | (tx << 16);
            g_bw[ee * NB + pos] = val[tx] * invw;
        }
        if (tx == 0) atomicAdd(entA, ent);
    }
    __syncthreads();
    if (tid == 0) atomicAdd(&g_entropy, *entA);
}

// ---------------- kernel 3: routed fused 3-layer expert MLP ----------------
__global__ void __launch_bounds__(256, 1) expert_kernel(
    const float* __restrict__ eW1, const float* __restrict__ eb1,
    const float* __restrict__ eW2, const float* __restrict__ eb2,
    const float* __restrict__ eW3, const float* __restrict__ eb3)
{
    extern __shared__ float smem[];
    int e = blockIdx.y;
    int cnt = g_count[e];
    int base = blockIdx.x * 64;
    if (base >= cnt) return;

    float* Xs   = smem;                   // 64*340 (also reused as L2 output, ld 260)
    float* Bs   = Xs + 64 * 340;          // 64*260
    float* Ws0  = Bs + 64 * 260;          // 32*256
    float* Ws1  = Ws0 + 32 * 256;         // 32*256
    float* swt  = Ws1 + 32 * 256;         // 64
    int*   srow = (int*)(swt + 64);       // 64

    int tid = threadIdx.x, ty = tid >> 5, tx = tid & 31;
    if (tid < 64) {
        int gi = base + tid;
        int gj = (gi < cnt) ? gi : (cnt - 1);
        srow[tid] = g_bucket[e * NB + gj];
        swt[tid]  = (gi < cnt) ? g_bw[e * NB + gj] : 0.f;
    }
    __syncthreads();
#pragma unroll
    for (int rr = 0; rr < 8; rr++) {
        int m = ty * 8 + rr;
        int rid = srow[m] & 0xFFFF;
        const float* src = g_inp + (size_t)rid * IND;
        for (int k = tx; k < IND; k += 32) Xs[m * 340 + k] = src[k];
    }

    unsigned long long acc[8][4];
    gemm64x256p<340>(Xs, IND, eW1 + (size_t)e * IND * HD, Ws0, Ws1, acc, ty, tx, tid);
    store_act_p(acc, eb1 + e * HD, Bs, 260, ty, tx, 0);

    gemm64x256p<260>(Bs, HD, eW2 + (size_t)e * HD * HD, Ws0, Ws1, acc, ty, tx, tid);
    store_act_p(acc, eb2 + e * HD, Xs, 260, ty, tx, 0);   // reuse Xs, ld=260

    gemm64x256p<260>(Xs, HD, eW3 + (size_t)e * HD * HD, Ws0, Ws1, acc, ty, tx, tid);

    const float* b3 = eb3 + e * HD;
    const int tx4 = tx << 2;
    float bs[8];
#pragma unroll
    for (int i = 0; i < 4; i++) { bs[i] = __ldg(&b3[tx4 + i]); bs[4 + i] = __ldg(&b3[128 + tx4 + i]); }
#pragma unroll
    for (int mi = 0; mi < 8; mi++) {
        int m = ty * 8 + mi;
        int gi = base + m;
        if (gi < cnt) {
            int packed = srow[m];
            int row = packed & 0xFFFF;
            int slot = packed >> 16;
            float w = swt[m];
            float* dst = g_eout + ((size_t)(row * 4 + slot)) * HD;
            float2 p0 = unpack2(acc[mi][0]);
            float2 p1 = unpack2(acc[mi][1]);
            float2 p2 = unpack2(acc[mi][2]);
            float2 p3 = unpack2(acc[mi][3]);
            float4 v0, v1;
            v0.x = w * mishf(p0.x + bs[0]);
            v0.y = w * mishf(p0.y + bs[1]);
            v0.z = w * mishf(p1.x + bs[2]);
            v0.w = w * mishf(p1.y + bs[3]);
            v1.x = w * mishf(p2.x + bs[4]);
            v1.y = w * mishf(p2.y + bs[5]);
            v1.z = w * mishf(p3.x + bs[6]);
            v1.w = w * mishf(p3.y + bs[7]);
            *(float4*)&dst[tx4]       = v0;
            *(float4*)&dst[128 + tx4] = v1;
        }
    }
}

// ---------------- kernel 4: combine slots + final linear + epilogue ----------------
__global__ void __launch_bounds__(256, 1) final_kernel(
    const float* __restrict__ x, const float* __restrict__ fW,
    const float* __restrict__ fb, float* __restrict__ out)
{
    extern __shared__ float smem[];
    float* cs  = smem;             // 64*260
    float* fWs = cs + 64 * 260;    // 256*64
    int tid = threadIdx.x;
    int base = blockIdx.x * 64;

    for (int i = tid; i < 4096; i += 256)
        ((float4*)fWs)[i] = ((const float4*)fW)[i];
    for (int idx = tid; idx < 64 * 256; idx += 256) {
        int m = idx >> 8, n = idx & 255;
        size_t rb = ((size_t)(base + m)) * 4 * HD + n;
        float v = g_eout[rb] + g_eout[rb + 256] + g_eout[rb + 512] + g_eout[rb + 768];
        cs[m * 260 + n] = v;
    }
    __syncthreads();

    int ty = tid >> 4, tx = tid & 15;
    float acc[4][4];
#pragma unroll
    for (int mi = 0; mi < 4; mi++)
#pragma unroll
        for (int ci = 0; ci < 4; ci++) acc[mi][ci] = 0.f;
#pragma unroll 4
    for (int k = 0; k < 256; k++) {
        float4 b = *(const float4*)&fWs[k * 64 + (tx << 2)];
#pragma unroll
        for (int mi = 0; mi < 4; mi++) {
            float a = cs[(ty * 4 + mi) * 260 + k];
            acc[mi][0] = fmaf(a, b.x, acc[mi][0]);
            acc[mi][1] = fmaf(a, b.y, acc[mi][1]);
            acc[mi][2] = fmaf(a, b.z, acc[mi][2]);
            acc[mi][3] = fmaf(a, b.w, acc[mi][3]);
        }
    }
#pragma unroll
    for (int mi = 0; mi < 4; mi++) {
        int row = base + ty * 4 + mi;
        float co = g_cout[row], ck = g_cskip[row];
        float4 xr = *(const float4*)&x[row * 64 + (tx << 2)];
        float4 o;
        o.x = fminf(fmaxf(co * (acc[mi][0] + __ldg(&fb[(tx << 2) + 0])) + ck * xr.x, -1.f), 1.f);
        o.y = fminf(fmaxf(co * (acc[mi][1] + __ldg(&fb[(tx << 2) + 1])) + ck * xr.y, -1.f), 1.f);
        o.z = fminf(fmaxf(co * (acc[mi][2] + __ldg(&fb[(tx << 2) + 2])) + ck * xr.z, -1.f), 1.f);
        o.w = fminf(fmaxf(co * (acc[mi][3] + __ldg(&fb[(tx << 2) + 3])) + ck * xr.w, -1.f), 1.f);
        *(float4*)&out[row * 64 + (tx << 2)] = o;
    }
}

// ---------------- kernel 5: aux loss ----------------
__global__ void aux_kernel(float* __restrict__ out, int out_size)
{
    if (threadIdx.x == 0 && out_size > NB * NACT) {
        float load[NE], mean = 0.f;
#pragma unroll
        for (int e = 0; e < NE; e++) { load[e] = (float)g_count[e] / (32768.0f + 1e-9f); mean += load[e]; }
        mean *= (1.0f / NE);
        float var = 0.f;
#pragma unroll
        for (int e = 0; e < NE; e++) { float d = load[e] - mean; var += d * d; }
        var *= (1.0f / (NE - 1));
        out[NB * NACT] = var + g_entropy / 32768.0f;
    }
}

extern "C" void kernel_launch(void* const* d_in, const int* in_sizes, int n_in,
                              void* d_out, int out_size)
{
    const float* x     = (const float*)d_in[0];
    const float* sigma = (const float*)d_in[1];
    const float* state = (const float*)d_in[2];
    const float* tW1 = (const float*)d_in[3];
    const float* tb1 = (const float*)d_in[4];
    const float* tW2 = (const float*)d_in[5];
    const float* tb2 = (const float*)d_in[6];
    const float* gW1 = (const float*)d_in[7];
    const float* gb1 = (const float*)d_in[8];
    const float* gW2 = (const float*)d_in[9];
    const float* gb2 = (const float*)d_in[10];
    const float* eW1 = (const float*)d_in[11];
    const float* eb1 = (const float*)d_in[12];
    const float* eW2 = (const float*)d_in[13];
    const float* eb2 = (const float*)d_in[14];
    const float* eW3 = (const float*)d_in[15];
    const float* eb3 = (const float*)d_in[16];
    const float* fW  = (const float*)d_in[17];
    const float* fb  = (const float*)d_in[18];
    float* out = (float*)d_out;

    const int gateSmem = (64 * 340 + 64 * 260 + 2 * 32 * 256 + 16) * 4;
    const int expSmem  = (64 * 340 + 64 * 260 + 2 * 32 * 256 + 64 + 64 + 16) * 4;
    const int finSmem  = (64 * 260 + 256 * 64 + 16) * 4;
    cudaFuncSetAttribute(gate_kernel,   cudaFuncAttributeMaxDynamicSharedMemorySize, gateSmem);
    cudaFuncSetAttribute(expert_kernel, cudaFuncAttributeMaxDynamicSharedMemorySize, expSmem);
    cudaFuncSetAttribute(final_kernel,  cudaFuncAttributeMaxDynamicSharedMemorySize, finSmem);

    prep_kernel<<<NB / 8, 256>>>(x, sigma, state, tW1, tb1, tW2, tb2);
    gate_kernel<<<NB / 64, 256, gateSmem>>>(gW1, gb1, gW2, gb2);
    expert_kernel<<<dim3(NB / 64, NE), 256, expSmem>>>(eW1, eb1, eW2, eb2, eW3, eb3);
    final_kernel<<<NB / 64, 256, finSmem>>>(x, fW, fb, out);
    aux_kernel<<<1, 32>>>(out, out_size);
}

// round 3
// speedup vs baseline: 1.2811x; 1.2051x over previous
#include <cuda_runtime.h>
#include <math.h>

#define NB   32768
#define IND  336
#define HD   256
#define NE   16
#define NACT 64

// ---------------- device scratch (no allocations allowed) ----------------
__device__ float g_inp[(size_t)NB * IND];       // staged input rows [B,336]
__device__ float g_cskip[NB];
__device__ float g_cout[NB];
__device__ int   g_count[NE];
__device__ float g_entropy;
__device__ int   g_bucket[NE * NB];             // packed row | slot<<16
__device__ float g_bw[NE * NB];                 // normalized gate weight
__device__ float g_comb[(size_t)NB * HD];       // combined expert output (atomic accum)

// fast exact-algebra mish: x*tanh(softplus(x)) == x*(w-1)/(w+1), w=(1+e^x)^2
__device__ __forceinline__ float mishf(float v) {
    if (v > 20.f) return v;
    float u = __expf(v);
    float w = 1.f + u;
    w = w * w;
    return v * __fdividef(w - 1.f, w + 1.f);
}

// packed fp32x2 FMA (sm_103a FFMA2)
#define FMA2(d, a, b) asm("fma.rn.f32x2 %0, %1, %2, %0;" : "+l"(d) : "l"(a), "l"(b))

__device__ __forceinline__ unsigned long long dup2(float v) {
    unsigned long long r;
    asm("mov.b64 %0, {%1, %1};" : "=l"(r) : "r"(__float_as_uint(v)));
    return r;
}
__device__ __forceinline__ float2 unpack2(unsigned long long v) {
    float2 r;
    asm("mov.b64 {%0, %1}, %2;" : "=f"(r.x), "=f"(r.y) : "l"(v));
    return r;
}

// ---------------- shared 64x256 packed-fp32 GEMM ----------------
// Block: 256 threads. warp ty (0..7) owns rows ty*8..+7; lane tx owns cols
// tx*4..+3 and 128+tx*4..+3 as f32x2 pairs. W tile double-buffered; exactly
// ONE __syncthreads per k-tile:
//   prefetch(0); bar; loop t { store(t); bar; prefetch(t+1); compute(t) }
// store(t) into buf[t&1] cannot race compute(t-2) on the same buf because
// every warp's store(t) is after barrier(t-1), which follows all compute(t-2).
template<int LDA>
__device__ __forceinline__ void gemm64x256p(
    const float* __restrict__ A, int K,
    const float* __restrict__ Wg, float* __restrict__ Ws0, float* __restrict__ Ws1,
    unsigned long long (&acc)[8][4], int ty, int tx, int tid)
{
#pragma unroll
    for (int mi = 0; mi < 8; mi++)
#pragma unroll
        for (int ni = 0; ni < 4; ni++) acc[mi][ni] = 0ull;

    const float* Abase = A + ty * 8 * LDA;
    const int ntiles = (K + 31) >> 5;
    const int tx4 = tx << 2;

    float4 pf[8];
    int pr[8], pc[8];
#pragma unroll
    for (int i = 0; i < 8; i++) {
        int f4 = i * 256 + tid;
        pr[i] = f4 >> 6;
        pc[i] = (f4 & 63) << 2;
    }
#pragma unroll
    for (int i = 0; i < 8; i++) {
        int k = pr[i];
        pf[i] = (k < K) ? *(const float4*)&Wg[(size_t)k * 256 + pc[i]]
                        : make_float4(0.f, 0.f, 0.f, 0.f);
    }
    __syncthreads();   // entry: prior phase's smem reads/writes all complete

    for (int t = 0; t < ntiles; t++) {
        float* Ws = (t & 1) ? Ws1 : Ws0;
#pragma unroll
        for (int i = 0; i < 8; i++)
            *(float4*)&Ws[pr[i] * 256 + pc[i]] = pf[i];
        __syncthreads();
        if (t + 1 < ntiles) {
            int kt = (t + 1) << 5;
#pragma unroll
            for (int i = 0; i < 8; i++) {
                int k = kt + pr[i];
                pf[i] = (k < K) ? *(const float4*)&Wg[(size_t)k * 256 + pc[i]]
                                : make_float4(0.f, 0.f, 0.f, 0.f);
            }
        }
        int kt = t << 5;
        int kc = min(32, K - kt);           // 32 or 16 (always even)
        const float* Ap = Abase + kt;
        for (int k = 0; k < kc; k += 2) {
            float2 a01[8];
#pragma unroll
            for (int mi = 0; mi < 8; mi++)
                a01[mi] = *(const float2*)&Ap[mi * LDA + k];
#pragma unroll
            for (int kk = 0; kk < 2; kk++) {
                const float* wrow = &Ws[(k + kk) * 256];
                ulonglong2 bb0 = *(const ulonglong2*)&wrow[tx4];
                ulonglong2 bb1 = *(const ulonglong2*)&wrow[128 + tx4];
#pragma unroll
                for (int mi = 0; mi < 8; mi++) {
                    unsigned long long a2 = dup2(kk ? a01[mi].y : a01[mi].x);
                    FMA2(acc[mi][0], a2, bb0.x);
                    FMA2(acc[mi][1], a2, bb0.y);
                    FMA2(acc[mi][2], a2, bb1.x);
                    FMA2(acc[mi][3], a2, bb1.y);
                }
            }
        }
    }
}

// mode 0: mish, mode 1: relu
__device__ __forceinline__ void store_act_p(
    unsigned long long (&acc)[8][4], const float* __restrict__ bias,
    float* __restrict__ Out, int ldo, int ty, int tx, int mode)
{
    const int tx4 = tx << 2;
    float bs[8];
#pragma unroll
    for (int i = 0; i < 4; i++) { bs[i] = __ldg(&bias[tx4 + i]); bs[4 + i] = __ldg(&bias[128 + tx4 + i]); }
#pragma unroll
    for (int mi = 0; mi < 8; mi++) {
        float* o = Out + (ty * 8 + mi) * ldo;
        float2 p0 = unpack2(acc[mi][0]);
        float2 p1 = unpack2(acc[mi][1]);
        float2 p2 = unpack2(acc[mi][2]);
        float2 p3 = unpack2(acc[mi][3]);
        float n[8] = { p0.x + bs[0], p0.y + bs[1], p1.x + bs[2], p1.y + bs[3],
                       p2.x + bs[4], p2.y + bs[5], p3.x + bs[6], p3.y + bs[7] };
        float4 v0, v1;
        if (mode == 0) {
            v0.x = mishf(n[0]); v0.y = mishf(n[1]); v0.z = mishf(n[2]); v0.w = mishf(n[3]);
            v1.x = mishf(n[4]); v1.y = mishf(n[5]); v1.z = mishf(n[6]); v1.w = mishf(n[7]);
        } else {
            v0.x = fmaxf(n[0], 0.f); v0.y = fmaxf(n[1], 0.f); v0.z = fmaxf(n[2], 0.f); v0.w = fmaxf(n[3], 0.f);
            v1.x = fmaxf(n[4], 0.f); v1.y = fmaxf(n[5], 0.f); v1.z = fmaxf(n[6], 0.f); v1.w = fmaxf(n[7], 0.f);
        }
        *(float4*)&o[tx4]       = v0;
        *(float4*)&o[128 + tx4] = v1;
    }
}

// ---------------- kernel 1: per-row prep (scalings + time MLP + zero g_comb) ----------------
__global__ void prep_kernel(
    const float* __restrict__ x, const float* __restrict__ sigma,
    const float* __restrict__ state,
    const float* __restrict__ tW1, const float* __restrict__ tb1,
    const float* __restrict__ tW2, const float* __restrict__ tb2)
{
    if (blockIdx.x == 0 && threadIdx.x < NE) g_count[threadIdx.x] = 0;
    if (blockIdx.x == 0 && threadIdx.x == NE) g_entropy = 0.f;

    // zero the combine buffer: 8Mi floats = 2Mi float4, 1Mi threads -> 2 each
    {
        int gt = blockIdx.x * blockDim.x + threadIdx.x;
        float4* c4 = (float4*)g_comb;
        c4[gt] = make_float4(0.f, 0.f, 0.f, 0.f);
        c4[gt + (NB * HD / 8)] = make_float4(0.f, 0.f, 0.f, 0.f);
    }

    int wid  = (blockIdx.x * blockDim.x + threadIdx.x) >> 5;
    int lane = threadIdx.x & 31;
    if (wid >= NB) return;
    int r = wid;

    float sg  = __ldg(&sigma[r]);
    float sd2 = 0.25f;
    float d   = sg - 0.002f;
    float cskip = sd2 / (d * d + sd2);
    float inv = rsqrtf(sg * sg + sd2);
    float cout = d * 0.5f * inv;
    float cin  = inv;
    float rt   = 250.0f * logf(sg + 1e-44f);

    const float FR[8] = { 1.0f, 0.26826957952797246f, 0.07196856730011519f,
                          0.019306977288832496f, 0.005179474679231212f,
                          0.0013894954943731375f, 0.00037275937203149404f,
                          0.0001f };
    float pe[16];
#pragma unroll
    for (int i = 0; i < 8; i++) {
        float s, c;
        sincosf(rt * FR[i], &s, &c);
        pe[i] = s; pe[i + 8] = c;
    }
    float h1 = __ldg(&tb1[lane]);
#pragma unroll
    for (int i = 0; i < 16; i++) h1 = fmaf(pe[i], __ldg(&tW1[i * 32 + lane]), h1);
    {   // exact-precision mish for the tiny time MLP (keep libm here, cheap)
        float sp = (h1 > 20.f) ? h1 : log1pf(expf(h1));
        h1 = h1 * tanhf(sp);
    }
    float tacc = (lane < 16) ? __ldg(&tb2[lane]) : 0.f;
#pragma unroll
    for (int j = 0; j < 32; j++) {
        float hj = __shfl_sync(0xffffffffu, h1, j);
        if (lane < 16) tacc = fmaf(hj, __ldg(&tW2[j * 16 + lane]), tacc);
    }
    float* row = g_inp + (size_t)r * IND;
    row[lane]      = cin * __ldg(&x[r * 64 + lane]);
    row[32 + lane] = cin * __ldg(&x[r * 64 + 32 + lane]);
    if (lane < 16) row[64 + lane] = tacc;
#pragma unroll
    for (int i = 0; i < 8; i++)
        row[80 + lane + i * 32] = __ldg(&state[r * 256 + lane + i * 32]);
    if (lane == 0) { g_cskip[r] = cskip; g_cout[r] = cout; }
}

// ---------------- kernel 2: gate + softmax + top4 + routing ----------------
__global__ void __launch_bounds__(256, 1) gate_kernel(
    const float* __restrict__ gW1, const float* __restrict__ gb1,
    const float* __restrict__ gW2, const float* __restrict__ gb2)
{
    extern __shared__ float smem[];
    float* Xs   = smem;                  // 64*340
    float* G1   = Xs + 64 * 340;         // 64*260
    float* Ws0  = G1 + 64 * 260;         // 32*256 (front 4096 reused as W2s later)
    float* Ws1  = Ws0 + 32 * 256;        // 32*256
    float* entA = Ws1 + 32 * 256;        // 1

    int tid = threadIdx.x, ty = tid >> 5, tx = tid & 31;
    int base = blockIdx.x * 64;
    if (tid == 0) *entA = 0.f;
#pragma unroll
    for (int rr = 0; rr < 8; rr++) {
        int m = ty * 8 + rr;
        const float* src = g_inp + (size_t)(base + m) * IND;
        for (int k = tx; k < IND; k += 32) Xs[m * 340 + k] = src[k];
    }
    unsigned long long acc[8][4];
    gemm64x256p<340>(Xs, IND, gW1, Ws0, Ws1, acc, ty, tx, tid);
    store_act_p(acc, gb1, G1, 260, ty, tx, /*relu*/1);
    __syncthreads();

    float* W2s = Ws0;
    for (int i = tid; i < 4096; i += 256) W2s[i] = gW2[i];
    __syncthreads();

    // layer2: 256 -> 16, per-warp per-row
    int j = tx & 15, kh = tx >> 4;
    for (int rr = 0; rr < 8; rr++) {
        int m = ty * 8 + rr;
        int row = base + m;
        const float* g1 = &G1[m * 260];
        float s = 0.f;
        int k0 = kh * 128;
#pragma unroll 4
        for (int k = 0; k < 128; k++) s = fmaf(g1[k0 + k], W2s[(k0 + k) * 16 + j], s);
        s += __shfl_down_sync(0xffffffffu, s, 16);
        float gv = s + __ldg(&gb2[j]);
        float p[16];
#pragma unroll
        for (int q = 0; q < 16; q++) p[q] = __shfl_sync(0xffffffffu, gv, q);
        float mx = p[0];
#pragma unroll
        for (int q = 1; q < 16; q++) mx = fmaxf(mx, p[q]);
        float Z = 0.f;
#pragma unroll
        for (int q = 0; q < 16; q++) { p[q] = expf(p[q] - mx); Z += p[q]; }
        float invZ = 1.f / Z;
        float ent = 0.f;
#pragma unroll
        for (int q = 0; q < 16; q++) { p[q] *= invZ; ent -= p[q] * logf(p[q] + 1e-9f); }
        unsigned usedm = 0;
        int   idx[4]; float val[4]; float wsum = 0.f;
#pragma unroll
        for (int s4 = 0; s4 < 4; s4++) {
            int best = 0; float bv = -1.f;
#pragma unroll
            for (int q = 0; q < 16; q++) {
                bool free = !((usedm >> q) & 1u);
                if (free && p[q] > bv) { bv = p[q]; best = q; }
            }
            usedm |= (1u << best);
            idx[s4] = best; val[s4] = bv; wsum += bv;
        }
        float invw = 1.f / (wsum + 1e-9f);
        if (tx < 4) {
            int ee = idx[tx];
            int pos = atomicAdd(&g_count[ee], 1);
            g_bucket[ee * NB + pos] = row | (tx << 16);
            g_bw[ee * NB + pos] = val[tx] * invw;
        }
        if (tx == 0) atomicAdd(entA, ent);
    }
    __syncthreads();
    if (tid == 0) atomicAdd(&g_entropy, *entA);
}

// ---------------- kernel 3: routed fused 3-layer expert MLP + atomic combine ----------------
__global__ void __launch_bounds__(256, 1) expert_kernel(
    const float* __restrict__ eW1, const float* __restrict__ eb1,
    const float* __restrict__ eW2, const float* __restrict__ eb2,
    const float* __restrict__ eW3, const float* __restrict__ eb3)
{
    extern __shared__ float smem[];
    int e = blockIdx.y;
    int cnt = g_count[e];
    int base = blockIdx.x * 64;
    if (base >= cnt) return;

    float* Xs   = smem;                   // 64*340 (reused as L2 output, ld 260)
    float* Bs   = Xs + 64 * 340;          // 64*260
    float* Ws0  = Bs + 64 * 260;          // 32*256
    float* Ws1  = Ws0 + 32 * 256;         // 32*256
    float* swt  = Ws1 + 32 * 256;         // 64
    int*   srow = (int*)(swt + 64);       // 64

    int tid = threadIdx.x, ty = tid >> 5, tx = tid & 31;
    if (tid < 64) {
        int gi = base + tid;
        int gj = (gi < cnt) ? gi : (cnt - 1);
        srow[tid] = g_bucket[e * NB + gj];
        swt[tid]  = (gi < cnt) ? g_bw[e * NB + gj] : 0.f;
    }
    __syncthreads();
#pragma unroll
    for (int rr = 0; rr < 8; rr++) {
        int m = ty * 8 + rr;
        int rid = srow[m] & 0xFFFF;
        const float* src = g_inp + (size_t)rid * IND;
        for (int k = tx; k < IND; k += 32) Xs[m * 340 + k] = src[k];
    }

    unsigned long long acc[8][4];
    gemm64x256p<340>(Xs, IND, eW1 + (size_t)e * IND * HD, Ws0, Ws1, acc, ty, tx, tid);
    store_act_p(acc, eb1 + e * HD, Bs, 260, ty, tx, 0);

    gemm64x256p<260>(Bs, HD, eW2 + (size_t)e * HD * HD, Ws0, Ws1, acc, ty, tx, tid);
    store_act_p(acc, eb2 + e * HD, Xs, 260, ty, tx, 0);   // reuse Xs, ld=260

    gemm64x256p<260>(Xs, HD, eW3 + (size_t)e * HD * HD, Ws0, Ws1, acc, ty, tx, tid);

    const float* b3 = eb3 + e * HD;
    const int tx4 = tx << 2;
    float bs[8];
#pragma unroll
    for (int i = 0; i < 4; i++) { bs[i] = __ldg(&b3[tx4 + i]); bs[4 + i] = __ldg(&b3[128 + tx4 + i]); }
#pragma unroll
    for (int mi = 0; mi < 8; mi++) {
        int m = ty * 8 + mi;
        int gi = base + m;
        if (gi < cnt) {
            int row = srow[m] & 0xFFFF;
            float w = swt[m];
            float* dst = g_comb + (size_t)row * HD;
            float2 p0 = unpack2(acc[mi][0]);
            float2 p1 = unpack2(acc[mi][1]);
            float2 p2 = unpack2(acc[mi][2]);
            float2 p3 = unpack2(acc[mi][3]);
            atomicAdd(&dst[tx4 + 0],       w * mishf(p0.x + bs[0]));
            atomicAdd(&dst[tx4 + 1],       w * mishf(p0.y + bs[1]));
            atomicAdd(&dst[tx4 + 2],       w * mishf(p1.x + bs[2]));
            atomicAdd(&dst[tx4 + 3],       w * mishf(p1.y + bs[3]));
            atomicAdd(&dst[128 + tx4 + 0], w * mishf(p2.x + bs[4]));
            atomicAdd(&dst[128 + tx4 + 1], w * mishf(p2.y + bs[5]));
            atomicAdd(&dst[128 + tx4 + 2], w * mishf(p3.x + bs[6]));
            atomicAdd(&dst[128 + tx4 + 3], w * mishf(p3.y + bs[7]));
        }
    }
}

// ---------------- kernel 4: final linear + epilogue ----------------
__global__ void __launch_bounds__(256, 1) final_kernel(
    const float* __restrict__ x, const float* __restrict__ fW,
    const float* __restrict__ fb, float* __restrict__ out)
{
    extern __shared__ float smem[];
    float* cs  = smem;             // 64*260
    float* fWs = cs + 64 * 260;    // 256*64
    int tid = threadIdx.x;
    int base = blockIdx.x * 64;

    for (int i = tid; i < 4096; i += 256)
        ((float4*)fWs)[i] = ((const float4*)fW)[i];
    for (int idx = tid; idx < 64 * 64; idx += 256) {
        int m = idx >> 6, n4 = (idx & 63) << 2;
        float4 v = *(const float4*)&g_comb[((size_t)(base + m)) * HD + n4];
        *(float4*)&cs[m * 260 + n4] = v;
    }
    __syncthreads();

    int ty = tid >> 4, tx = tid & 15;
    float acc[4][4];
#pragma unroll
    for (int mi = 0; mi < 4; mi++)
#pragma unroll
        for (int ci = 0; ci < 4; ci++) acc[mi][ci] = 0.f;
#pragma unroll 4
    for (int k = 0; k < 256; k++) {
        float4 b = *(const float4*)&fWs[k * 64 + (tx << 2)];
#pragma unroll
        for (int mi = 0; mi < 4; mi++) {
            float a = cs[(ty * 4 + mi) * 260 + k];
            acc[mi][0] = fmaf(a, b.x, acc[mi][0]);
            acc[mi][1] = fmaf(a, b.y, acc[mi][1]);
            acc[mi][2] = fmaf(a, b.z, acc[mi][2]);
            acc[mi][3] = fmaf(a, b.w, acc[mi][3]);
        }
    }
#pragma unroll
    for (int mi = 0; mi < 4; mi++) {
        int row = base + ty * 4 + mi;
        float co = g_cout[row], ck = g_cskip[row];
        float4 xr = *(const float4*)&x[row * 64 + (tx << 2)];
        float4 o;
        o.x = fminf(fmaxf(co * (acc[mi][0] + __ldg(&fb[(tx << 2) + 0])) + ck * xr.x, -1.f), 1.f);
        o.y = fminf(fmaxf(co * (acc[mi][1] + __ldg(&fb[(tx << 2) + 1])) + ck * xr.y, -1.f), 1.f);
        o.z = fminf(fmaxf(co * (acc[mi][2] + __ldg(&fb[(tx << 2) + 2])) + ck * xr.z, -1.f), 1.f);
        o.w = fminf(fmaxf(co * (acc[mi][3] + __ldg(&fb[(tx << 2) + 3])) + ck * xr.w, -1.f), 1.f);
        *(float4*)&out[row * 64 + (tx << 2)] = o;
    }
}

// ---------------- kernel 5: aux loss ----------------
__global__ void aux_kernel(float* __restrict__ out, int out_size)
{
    if (threadIdx.x == 0 && out_size > NB * NACT) {
        float load[NE], mean = 0.f;
#pragma unroll
        for (int e = 0; e < NE; e++) { load[e] = (float)g_count[e] / (32768.0f + 1e-9f); mean += load[e]; }
        mean *= (1.0f / NE);
        float var = 0.f;
#pragma unroll
        for (int e = 0; e < NE; e++) { float d = load[e] - mean; var += d * d; }
        var *= (1.0f / (NE - 1));
        out[NB * NACT] = var + g_entropy / 32768.0f;
    }
}

extern "C" void kernel_launch(void* const* d_in, const int* in_sizes, int n_in,
                              void* d_out, int out_size)
{
    const float* x     = (const float*)d_in[0];
    const float* sigma = (const float*)d_in[1];
    const float* state = (const float*)d_in[2];
    const float* tW1 = (const float*)d_in[3];
    const float* tb1 = (const float*)d_in[4];
    const float* tW2 = (const float*)d_in[5];
    const float* tb2 = (const float*)d_in[6];
    const float* gW1 = (const float*)d_in[7];
    const float* gb1 = (const float*)d_in[8];
    const float* gW2 = (const float*)d_in[9];
    const float* gb2 = (const float*)d_in[10];
    const float* eW1 = (const float*)d_in[11];
    const float* eb1 = (const float*)d_in[12];
    const float* eW2 = (const float*)d_in[13];
    const float* eb2 = (const float*)d_in[14];
    const float* eW3 = (const float*)d_in[15];
    const float* eb3 = (const float*)d_in[16];
    const float* fW  = (const float*)d_in[17];
    const float* fb  = (const float*)d_in[18];
    float* out = (float*)d_out;

    const int gateSmem = (64 * 340 + 64 * 260 + 2 * 32 * 256 + 16) * 4;
    const int expSmem  = (64 * 340 + 64 * 260 + 2 * 32 * 256 + 64 + 64 + 16) * 4;
    const int finSmem  = (64 * 260 + 256 * 64 + 16) * 4;
    cudaFuncSetAttribute(gate_kernel,   cudaFuncAttributeMaxDynamicSharedMemorySize, gateSmem);
    cudaFuncSetAttribute(expert_kernel, cudaFuncAttributeMaxDynamicSharedMemorySize, expSmem);
    cudaFuncSetAttribute(final_kernel,  cudaFuncAttributeMaxDynamicSharedMemorySize, finSmem);

    prep_kernel<<<NB / 8, 256>>>(x, sigma, state, tW1, tb1, tW2, tb2);
    gate_kernel<<<NB / 64, 256, gateSmem>>>(gW1, gb1, gW2, gb2);
    expert_kernel<<<dim3(NB / 64, NE), 256, expSmem>>>(eW1, eb1, eW2, eb2, eW3, eb3);
    final_kernel<<<NB / 64, 256, finSmem>>>(x, fW, fb, out);
    aux_kernel<<<1, 32>>>(out, out_size);
}

// round 4
// speedup vs baseline: 1.2813x; 1.0001x over previous
#include <cuda_runtime.h>
#include <math.h>

#define NB   32768
#define IND  336
#define HD   256
#define NE   16
#define NACT 64

// ---------------- device scratch (no allocations allowed) ----------------
__device__ float g_inp[(size_t)NB * IND];       // staged input rows [B,336]
__device__ float g_cskip[NB];
__device__ float g_cout[NB];
__device__ int   g_count[NE];
__device__ float g_entropy;
__device__ int   g_bucket[NE * NB];             // packed row | slot<<16
__device__ float g_bw[NE * NB];                 // normalized gate weight
__device__ float g_comb[(size_t)NB * HD];       // combined expert output (atomic accum)

// fast exact-algebra mish: x*tanh(softplus(x)) == x*(w-1)/(w+1), w=(1+e^x)^2
__device__ __forceinline__ float mishf(float v) {
    if (v > 20.f) return v;
    float u = __expf(v);
    float w = 1.f + u;
    w = w * w;
    return v * __fdividef(w - 1.f, w + 1.f);
}

// packed fp32x2 FMA (sm_103a FFMA2)
#define FMA2(d, a, b) asm("fma.rn.f32x2 %0, %1, %2, %0;" : "+l"(d) : "l"(a), "l"(b))

__device__ __forceinline__ unsigned long long dup2(float v) {
    unsigned long long r;
    asm("mov.b64 %0, {%1, %1};" : "=l"(r) : "r"(__float_as_uint(v)));
    return r;
}
__device__ __forceinline__ float2 unpack2(unsigned long long v) {
    float2 r;
    asm("mov.b64 {%0, %1}, %2;" : "=f"(r.x), "=f"(r.y) : "l"(v));
    return r;
}

// ---------------- shared 64x256 packed-fp32 GEMM ----------------
// Block: 256 threads. warp ty (0..7) owns rows ty*8..+7; lane tx owns cols
// tx*4..+3 and 128+tx*4..+3 as f32x2 pairs. W tile double-buffered; exactly
// ONE __syncthreads per k-tile:
//   prefetch(0); bar; loop t { store(t); bar; prefetch(t+1); compute(t) }
// store(t) into buf[t&1] cannot race compute(t-2) on the same buf because
// every warp's store(t) is after barrier(t-1), which follows all compute(t-2).
template<int LDA>
__device__ __forceinline__ void gemm64x256p(
    const float* __restrict__ A, int K,
    const float* __restrict__ Wg, float* __restrict__ Ws0, float* __restrict__ Ws1,
    unsigned long long (&acc)[8][4], int ty, int tx, int tid)
{
#pragma unroll
    for (int mi = 0; mi < 8; mi++)
#pragma unroll
        for (int ni = 0; ni < 4; ni++) acc[mi][ni] = 0ull;

    const float* Abase = A + ty * 8 * LDA;
    const int ntiles = (K + 31) >> 5;
    const int tx4 = tx << 2;

    float4 pf[8];
    int pr[8], pc[8];
#pragma unroll
    for (int i = 0; i < 8; i++) {
        int f4 = i * 256 + tid;
        pr[i] = f4 >> 6;
        pc[i] = (f4 & 63) << 2;
    }
#pragma unroll
    for (int i = 0; i < 8; i++) {
        int k = pr[i];
        pf[i] = (k < K) ? *(const float4*)&Wg[(size_t)k * 256 + pc[i]]
                        : make_float4(0.f, 0.f, 0.f, 0.f);
    }
    __syncthreads();   // entry: prior phase's smem reads/writes all complete

    for (int t = 0; t < ntiles; t++) {
        float* Ws = (t & 1) ? Ws1 : Ws0;
#pragma unroll
        for (int i = 0; i < 8; i++)
            *(float4*)&Ws[pr[i] * 256 + pc[i]] = pf[i];
        __syncthreads();
        if (t + 1 < ntiles) {
            int kt = (t + 1) << 5;
#pragma unroll
            for (int i = 0; i < 8; i++) {
                int k = kt + pr[i];
                pf[i] = (k < K) ? *(const float4*)&Wg[(size_t)k * 256 + pc[i]]
                                : make_float4(0.f, 0.f, 0.f, 0.f);
            }
        }
        int kt = t << 5;
        int kc = min(32, K - kt);           // 32 or 16 (always even)
        const float* Ap = Abase + kt;
        for (int k = 0; k < kc; k += 2) {
            float2 a01[8];
#pragma unroll
            for (int mi = 0; mi < 8; mi++)
                a01[mi] = *(const float2*)&Ap[mi * LDA + k];
#pragma unroll
            for (int kk = 0; kk < 2; kk++) {
                const float* wrow = &Ws[(k + kk) * 256];
                ulonglong2 bb0 = *(const ulonglong2*)&wrow[tx4];
                ulonglong2 bb1 = *(const ulonglong2*)&wrow[128 + tx4];
#pragma unroll
                for (int mi = 0; mi < 8; mi++) {
                    unsigned long long a2 = dup2(kk ? a01[mi].y : a01[mi].x);
                    FMA2(acc[mi][0], a2, bb0.x);
                    FMA2(acc[mi][1], a2, bb0.y);
                    FMA2(acc[mi][2], a2, bb1.x);
                    FMA2(acc[mi][3], a2, bb1.y);
                }
            }
        }
    }
}

// mode 0: mish, mode 1: relu
__device__ __forceinline__ void store_act_p(
    unsigned long long (&acc)[8][4], const float* __restrict__ bias,
    float* __restrict__ Out, int ldo, int ty, int tx, int mode)
{
    const int tx4 = tx << 2;
    float bs[8];
#pragma unroll
    for (int i = 0; i < 4; i++) { bs[i] = __ldg(&bias[tx4 + i]); bs[4 + i] = __ldg(&bias[128 + tx4 + i]); }
#pragma unroll
    for (int mi = 0; mi < 8; mi++) {
        float* o = Out + (ty * 8 + mi) * ldo;
        float2 p0 = unpack2(acc[mi][0]);
        float2 p1 = unpack2(acc[mi][1]);
        float2 p2 = unpack2(acc[mi][2]);
        float2 p3 = unpack2(acc[mi][3]);
        float n[8] = { p0.x + bs[0], p0.y + bs[1], p1.x + bs[2], p1.y + bs[3],
                       p2.x + bs[4], p2.y + bs[5], p3.x + bs[6], p3.y + bs[7] };
        float4 v0, v1;
        if (mode == 0) {
            v0.x = mishf(n[0]); v0.y = mishf(n[1]); v0.z = mishf(n[2]); v0.w = mishf(n[3]);
            v1.x = mishf(n[4]); v1.y = mishf(n[5]); v1.z = mishf(n[6]); v1.w = mishf(n[7]);
        } else {
            v0.x = fmaxf(n[0], 0.f); v0.y = fmaxf(n[1], 0.f); v0.z = fmaxf(n[2], 0.f); v0.w = fmaxf(n[3], 0.f);
            v1.x = fmaxf(n[4], 0.f); v1.y = fmaxf(n[5], 0.f); v1.z = fmaxf(n[6], 0.f); v1.w = fmaxf(n[7], 0.f);
        }
        *(float4*)&o[tx4]       = v0;
        *(float4*)&o[128 + tx4] = v1;
    }
}

// ---------------- kernel 1: per-row prep (scalings + time MLP + zero g_comb) ----------------
__global__ void prep_kernel(
    const float* __restrict__ x, const float* __restrict__ sigma,
    const float* __restrict__ state,
    const float* __restrict__ tW1, const float* __restrict__ tb1,
    const float* __restrict__ tW2, const float* __restrict__ tb2)
{
    if (blockIdx.x == 0 && threadIdx.x < NE) g_count[threadIdx.x] = 0;
    if (blockIdx.x == 0 && threadIdx.x == NE) g_entropy = 0.f;

    // zero the combine buffer: 8Mi floats = 2Mi float4, 1Mi threads -> 2 each
    {
        int gt = blockIdx.x * blockDim.x + threadIdx.x;
        float4* c4 = (float4*)g_comb;
        c4[gt] = make_float4(0.f, 0.f, 0.f, 0.f);
        c4[gt + (NB * HD / 8)] = make_float4(0.f, 0.f, 0.f, 0.f);
    }

    int wid  = (blockIdx.x * blockDim.x + threadIdx.x) >> 5;
    int lane = threadIdx.x & 31;
    if (wid >= NB) return;
    int r = wid;

    float sg  = __ldg(&sigma[r]);
    float sd2 = 0.25f;
    float d   = sg - 0.002f;
    float cskip = sd2 / (d * d + sd2);
    float inv = rsqrtf(sg * sg + sd2);
    float cout = d * 0.5f * inv;
    float cin  = inv;
    float rt   = 250.0f * logf(sg + 1e-44f);

    const float FR[8] = { 1.0f, 0.26826957952797246f, 0.07196856730011519f,
                          0.019306977288832496f, 0.005179474679231212f,
                          0.0013894954943731375f, 0.00037275937203149404f,
                          0.0001f };
    float pe[16];
#pragma unroll
    for (int i = 0; i < 8; i++) {
        float s, c;
        sincosf(rt * FR[i], &s, &c);
        pe[i] = s; pe[i + 8] = c;
    }
    float h1 = __ldg(&tb1[lane]);
#pragma unroll
    for (int i = 0; i < 16; i++) h1 = fmaf(pe[i], __ldg(&tW1[i * 32 + lane]), h1);
    {   // exact-precision mish for the tiny time MLP (keep libm here, cheap)
        float sp = (h1 > 20.f) ? h1 : log1pf(expf(h1));
        h1 = h1 * tanhf(sp);
    }
    float tacc = (lane < 16) ? __ldg(&tb2[lane]) : 0.f;
#pragma unroll
    for (int j = 0; j < 32; j++) {
        float hj = __shfl_sync(0xffffffffu, h1, j);
        if (lane < 16) tacc = fmaf(hj, __ldg(&tW2[j * 16 + lane]), tacc);
    }
    float* row = g_inp + (size_t)r * IND;
    row[lane]      = cin * __ldg(&x[r * 64 + lane]);
    row[32 + lane] = cin * __ldg(&x[r * 64 + 32 + lane]);
    if (lane < 16) row[64 + lane] = tacc;
#pragma unroll
    for (int i = 0; i < 8; i++)
        row[80 + lane + i * 32] = __ldg(&state[r * 256 + lane + i * 32]);
    if (lane == 0) { g_cskip[r] = cskip; g_cout[r] = cout; }
}

// ---------------- kernel 2: gate + softmax + top4 + routing ----------------
__global__ void __launch_bounds__(256, 1) gate_kernel(
    const float* __restrict__ gW1, const float* __restrict__ gb1,
    const float* __restrict__ gW2, const float* __restrict__ gb2)
{
    extern __shared__ float smem[];
    float* Xs   = smem;                  // 64*340
    float* G1   = Xs + 64 * 340;         // 64*260
    float* Ws0  = G1 + 64 * 260;         // 32*256 (front 4096 reused as W2s later)
    float* Ws1  = Ws0 + 32 * 256;        // 32*256
    float* entA = Ws1 + 32 * 256;        // 1

    int tid = threadIdx.x, ty = tid >> 5, tx = tid & 31;
    int base = blockIdx.x * 64;
    if (tid == 0) *entA = 0.f;
#pragma unroll
    for (int rr = 0; rr < 8; rr++) {
        int m = ty * 8 + rr;
        const float* src = g_inp + (size_t)(base + m) * IND;
        for (int k = tx; k < IND; k += 32) Xs[m * 340 + k] = src[k];
    }
    unsigned long long acc[8][4];
    gemm64x256p<340>(Xs, IND, gW1, Ws0, Ws1, acc, ty, tx, tid);
    store_act_p(acc, gb1, G1, 260, ty, tx, /*relu*/1);
    __syncthreads();

    float* W2s = Ws0;
    for (int i = tid; i < 4096; i += 256) W2s[i] = gW2[i];
    __syncthreads();

    // layer2: 256 -> 16, per-warp per-row
    int j = tx & 15, kh = tx >> 4;
    for (int rr = 0; rr < 8; rr++) {
        int m = ty * 8 + rr;
        int row = base + m;
        const float* g1 = &G1[m * 260];
        float s = 0.f;
        int k0 = kh * 128;
#pragma unroll 4
        for (int k = 0; k < 128; k++) s = fmaf(g1[k0 + k], W2s[(k0 + k) * 16 + j], s);
        s += __shfl_down_sync(0xffffffffu, s, 16);
        float gv = s + __ldg(&gb2[j]);
        float p[16];
#pragma unroll
        for (int q = 0; q < 16; q++) p[q] = __shfl_sync(0xffffffffu, gv, q);
        float mx = p[0];
#pragma unroll
        for (int q = 1; q < 16; q++) mx = fmaxf(mx, p[q]);
        float Z = 0.f;
#pragma unroll
        for (int q = 0; q < 16; q++) { p[q] = expf(p[q] - mx); Z += p[q]; }
        float invZ = 1.f / Z;
        float ent = 0.f;
#pragma unroll
        for (int q = 0; q < 16; q++) { p[q] *= invZ; ent -= p[q] * logf(p[q] + 1e-9f); }
        unsigned usedm = 0;
        int   idx[4]; float val[4]; float wsum = 0.f;
#pragma unroll
        for (int s4 = 0; s4 < 4; s4++) {
            int best = 0; float bv = -1.f;
#pragma unroll
            for (int q = 0; q < 16; q++) {
                bool free = !((usedm >> q) & 1u);
                if (free && p[q] > bv) { bv = p[q]; best = q; }
            }
            usedm |= (1u << best);
            idx[s4] = best; val[s4] = bv; wsum += bv;
        }
        float invw = 1.f / (wsum + 1e-9f);
        if (tx < 4) {
            int ee = idx[tx];
            int pos = atomicAdd(&g_count[ee], 1);
            g_bucket[ee * NB + pos] = row | (tx << 16);
            g_bw[ee * NB + pos] = val[tx] * invw;
        }
        if (tx == 0) atomicAdd(entA, ent);
    }
    __syncthreads();
    if (tid == 0) atomicAdd(&g_entropy, *entA);
}

// ---------------- kernel 3: routed fused 3-layer expert MLP + atomic combine ----------------
__global__ void __launch_bounds__(256, 1) expert_kernel(
    const float* __restrict__ eW1, const float* __restrict__ eb1,
    const float* __restrict__ eW2, const float* __restrict__ eb2,
    const float* __restrict__ eW3, const float* __restrict__ eb3)
{
    extern __shared__ float smem[];
    int e = blockIdx.y;
    int cnt = g_count[e];
    int base = blockIdx.x * 64;
    if (base >= cnt) return;

    float* Xs   = smem;                   // 64*340 (reused as L2 output, ld 260)
    float* Bs   = Xs + 64 * 340;          // 64*260
    float* Ws0  = Bs + 64 * 260;          // 32*256
    float* Ws1  = Ws0 + 32 * 256;         // 32*256
    float* swt  = Ws1 + 32 * 256;         // 64
    int*   srow = (int*)(swt + 64);       // 64

    int tid = threadIdx.x, ty = tid >> 5, tx = tid & 31;
    if (tid < 64) {
        int gi = base + tid;
        int gj = (gi < cnt) ? gi : (cnt - 1);
        srow[tid] = g_bucket[e * NB + gj];
        swt[tid]  = (gi < cnt) ? g_bw[e * NB + gj] : 0.f;
    }
    __syncthreads();
#pragma unroll
    for (int rr = 0; rr < 8; rr++) {
        int m = ty * 8 + rr;
        int rid = srow[m] & 0xFFFF;
        const float* src = g_inp + (size_t)rid * IND;
        for (int k = tx; k < IND; k += 32) Xs[m * 340 + k] = src[k];
    }

    unsigned long long acc[8][4];
    gemm64x256p<340>(Xs, IND, eW1 + (size_t)e * IND * HD, Ws0, Ws1, acc, ty, tx, tid);
    store_act_p(acc, eb1 + e * HD, Bs, 260, ty, tx, 0);

    gemm64x256p<260>(Bs, HD, eW2 + (size_t)e * HD * HD, Ws0, Ws1, acc, ty, tx, tid);
    store_act_p(acc, eb2 + e * HD, Xs, 260, ty, tx, 0);   // reuse Xs, ld=260

    gemm64x256p<260>(Xs, HD, eW3 + (size_t)e * HD * HD, Ws0, Ws1, acc, ty, tx, tid);

    const float* b3 = eb3 + e * HD;
    const int tx4 = tx << 2;
    float bs[8];
#pragma unroll
    for (int i = 0; i < 4; i++) { bs[i] = __ldg(&b3[tx4 + i]); bs[4 + i] = __ldg(&b3[128 + tx4 + i]); }
#pragma unroll
    for (int mi = 0; mi < 8; mi++) {
        int m = ty * 8 + mi;
        int gi = base + m;
        if (gi < cnt) {
            int row = srow[m] & 0xFFFF;
            float w = swt[m];
            float* dst = g_comb + (size_t)row * HD;
            float2 p0 = unpack2(acc[mi][0]);
            float2 p1 = unpack2(acc[mi][1]);
            float2 p2 = unpack2(acc[mi][2]);
            float2 p3 = unpack2(acc[mi][3]);
            atomicAdd(&dst[tx4 + 0],       w * mishf(p0.x + bs[0]));
            atomicAdd(&dst[tx4 + 1],       w * mishf(p0.y + bs[1]));
            atomicAdd(&dst[tx4 + 2],       w * mishf(p1.x + bs[2]));
            atomicAdd(&dst[tx4 + 3],       w * mishf(p1.y + bs[3]));
            atomicAdd(&dst[128 + tx4 + 0], w * mishf(p2.x + bs[4]));
            atomicAdd(&dst[128 + tx4 + 1], w * mishf(p2.y + bs[5]));
            atomicAdd(&dst[128 + tx4 + 2], w * mishf(p3.x + bs[6]));
            atomicAdd(&dst[128 + tx4 + 3], w * mishf(p3.y + bs[7]));
        }
    }
}

// ---------------- kernel 4: final linear + epilogue ----------------
__global__ void __launch_bounds__(256, 1) final_kernel(
    const float* __restrict__ x, const float* __restrict__ fW,
    const float* __restrict__ fb, float* __restrict__ out)
{
    extern __shared__ float smem[];
    float* cs  = smem;             // 64*260
    float* fWs = cs + 64 * 260;    // 256*64
    int tid = threadIdx.x;
    int base = blockIdx.x * 64;

    for (int i = tid; i < 4096; i += 256)
        ((float4*)fWs)[i] = ((const float4*)fW)[i];
    for (int idx = tid; idx < 64 * 64; idx += 256) {
        int m = idx >> 6, n4 = (idx & 63) << 2;
        float4 v = *(const float4*)&g_comb[((size_t)(base + m)) * HD + n4];
        *(float4*)&cs[m * 260 + n4] = v;
    }
    __syncthreads();

    int ty = tid >> 4, tx = tid & 15;
    float acc[4][4];
#pragma unroll
    for (int mi = 0; mi < 4; mi++)
#pragma unroll
        for (int ci = 0; ci < 4; ci++) acc[mi][ci] = 0.f;
#pragma unroll 4
    for (int k = 0; k < 256; k++) {
        float4 b = *(const float4*)&fWs[k * 64 + (tx << 2)];
#pragma unroll
        for (int mi = 0; mi < 4; mi++) {
            float a = cs[(ty * 4 + mi) * 260 + k];
            acc[mi][0] = fmaf(a, b.x, acc[mi][0]);
            acc[mi][1] = fmaf(a, b.y, acc[mi][1]);
            acc[mi][2] = fmaf(a, b.z, acc[mi][2]);
            acc[mi][3] = fmaf(a, b.w, acc[mi][3]);
        }
    }
#pragma unroll
    for (int mi = 0; mi < 4; mi++) {
        int row = base + ty * 4 + mi;
        float co = g_cout[row], ck = g_cskip[row];
        float4 xr = *(const float4*)&x[row * 64 + (tx << 2)];
        float4 o;
        o.x = fminf(fmaxf(co * (acc[mi][0] + __ldg(&fb[(tx << 2) + 0])) + ck * xr.x, -1.f), 1.f);
        o.y = fminf(fmaxf(co * (acc[mi][1] + __ldg(&fb[(tx << 2) + 1])) + ck * xr.y, -1.f), 1.f);
        o.z = fminf(fmaxf(co * (acc[mi][2] + __ldg(&fb[(tx << 2) + 2])) + ck * xr.z, -1.f), 1.f);
        o.w = fminf(fmaxf(co * (acc[mi][3] + __ldg(&fb[(tx << 2) + 3])) + ck * xr.w, -1.f), 1.f);
        *(float4*)&out[row * 64 + (tx << 2)] = o;
    }
}

// ---------------- kernel 5: aux loss ----------------
__global__ void aux_kernel(float* __restrict__ out, int out_size)
{
    if (threadIdx.x == 0 && out_size > NB * NACT) {
        float load[NE], mean = 0.f;
#pragma unroll
        for (int e = 0; e < NE; e++) { load[e] = (float)g_count[e] / (32768.0f + 1e-9f); mean += load[e]; }
        mean *= (1.0f / NE);
        float var = 0.f;
#pragma unroll
        for (int e = 0; e < NE; e++) { float d = load[e] - mean; var += d * d; }
        var *= (1.0f / (NE - 1));
        out[NB * NACT] = var + g_entropy / 32768.0f;
    }
}

extern "C" void kernel_launch(void* const* d_in, const int* in_sizes, int n_in,
                              void* d_out, int out_size)
{
    const float* x     = (const float*)d_in[0];
    const float* sigma = (const float*)d_in[1];
    const float* state = (const float*)d_in[2];
    const float* tW1 = (const float*)d_in[3];
    const float* tb1 = (const float*)d_in[4];
    const float* tW2 = (const float*)d_in[5];
    const float* tb2 = (const float*)d_in[6];
    const float* gW1 = (const float*)d_in[7];
    const float* gb1 = (const float*)d_in[8];
    const float* gW2 = (const float*)d_in[9];
    const float* gb2 = (const float*)d_in[10];
    const float* eW1 = (const float*)d_in[11];
    const float* eb1 = (const float*)d_in[12];
    const float* eW2 = (const float*)d_in[13];
    const float* eb2 = (const float*)d_in[14];
    const float* eW3 = (const float*)d_in[15];
    const float* eb3 = (const float*)d_in[16];
    const float* fW  = (const float*)d_in[17];
    const float* fb  = (const float*)d_in[18];
    float* out = (float*)d_out;

    const int gateSmem = (64 * 340 + 64 * 260 + 2 * 32 * 256 + 16) * 4;
    const int expSmem  = (64 * 340 + 64 * 260 + 2 * 32 * 256 + 64 + 64 + 16) * 4;
    const int finSmem  = (64 * 260 + 256 * 64 + 16) * 4;
    cudaFuncSetAttribute(gate_kernel,   cudaFuncAttributeMaxDynamicSharedMemorySize, gateSmem);
    cudaFuncSetAttribute(expert_kernel, cudaFuncAttributeMaxDynamicSharedMemorySize, expSmem);
    cudaFuncSetAttribute(final_kernel,  cudaFuncAttributeMaxDynamicSharedMemorySize, finSmem);

    prep_kernel<<<NB / 8, 256>>>(x, sigma, state, tW1, tb1, tW2, tb2);
    gate_kernel<<<NB / 64, 256, gateSmem>>>(gW1, gb1, gW2, gb2);
    expert_kernel<<<dim3(NB / 64, NE), 256, expSmem>>>(eW1, eb1, eW2, eb2, eW3, eb3);
    final_kernel<<<NB / 64, 256, finSmem>>>(x, fW, fb, out);
    aux_kernel<<<1, 32>>>(out, out_size);
}

// round 6
// speedup vs baseline: 1.3835x; 1.0798x over previous
#include <cuda_runtime.h>
#include <cuda_bf16.h>
#include <math.h>
#include <stdint.h>

#define NB   32768
#define IND  336
#define HD   256
#define NE   16
#define NACT 64

// ---------------- device scratch ----------------
__device__ float g_inp[(size_t)NB * IND];
__device__ float g_cskip[NB];
__device__ float g_cout[NB];
__device__ int   g_count[NE];
__device__ float g_entropy;
__device__ int   g_bucket[NE * NB];             // row | slot<<16
__device__ float g_bw[NE * NB];
__device__ float g_eout[(size_t)NB * 4 * HD];   // per-(row,slot) weighted expert out

// packed weights: [e][n][pair p]{hi(k2p),hi(k2p+1),lo(k2p),lo(k2p+1)} as u64
__device__ __align__(16) unsigned long long w1p[NE * HD * 168];
__device__ __align__(16) unsigned long long w2p[NE * HD * 128];
__device__ __align__(16) unsigned long long w3p[NE * HD * 128];

__device__ __forceinline__ float mishf(float v) {
    if (v > 20.f) return v;
    float u = __expf(v);
    float w = 1.f + u;
    w = w * w;
    return v * __fdividef(w - 1.f, w + 1.f);
}

// ---------------- packing helpers ----------------
__device__ __forceinline__ uint2 pack2(float a, float b) {
    __nv_bfloat16 ha = __float2bfloat16_rn(a), hb = __float2bfloat16_rn(b);
    __nv_bfloat16 la = __float2bfloat16_rn(a - __bfloat162float(ha));
    __nv_bfloat16 lb = __float2bfloat16_rn(b - __bfloat162float(hb));
    uint2 r;
    r.x = (uint32_t)*(unsigned short*)&ha | ((uint32_t)*(unsigned short*)&hb << 16);
    r.y = (uint32_t)*(unsigned short*)&la | ((uint32_t)*(unsigned short*)&lb << 16);
    return r;
}
__device__ __forceinline__ unsigned long long pack_u64(float a, float b) {
    uint2 r = pack2(a, b);
    return (unsigned long long)r.x | ((unsigned long long)r.y << 32);
}

// ---------------- mma.sync / cp.async (baseline PTX, works on compute_103) ----------------
__device__ __forceinline__ void mma_bf16(float* c, const uint32_t* a, uint32_t b0, uint32_t b1) {
    asm volatile(
        "mma.sync.aligned.m16n8k16.row.col.f32.bf16.bf16.f32 "
        "{%0,%1,%2,%3}, {%4,%5,%6,%7}, {%8,%9}, {%0,%1,%2,%3};"
        : "+f"(c[0]), "+f"(c[1]), "+f"(c[2]), "+f"(c[3])
        : "r"(a[0]), "r"(a[1]), "r"(a[2]), "r"(a[3]), "r"(b0), "r"(b1));
}
__device__ __forceinline__ uint32_t smem_u32(const void* p) {
    uint32_t a;
    asm("{ .reg .u64 t; cvta.to.shared.u64 t, %1; cvt.u32.u64 %0, t; }" : "=r"(a) : "l"(p));
    return a;
}
__device__ __forceinline__ void cpasync16(uint32_t dst, const void* src) {
    asm volatile("cp.async.cg.shared.global [%0], [%1], 16;" :: "r"(dst), "l"(src) : "memory");
}
#define CP_COMMIT() asm volatile("cp.async.commit_group;" ::: "memory")
#define CP_WAIT0()  asm volatile("cp.async.wait_group 0;" ::: "memory")

// ---------------- packed fp32x2 FMA machinery (gate kernel) ----------------
#define FMA2(d, a, b) asm("fma.rn.f32x2 %0, %1, %2, %0;" : "+l"(d) : "l"(a), "l"(b))
__device__ __forceinline__ unsigned long long dup2(float v) {
    unsigned long long r;
    asm("mov.b64 %0, {%1, %1};" : "=l"(r) : "r"(__float_as_uint(v)));
    return r;
}
__device__ __forceinline__ float2 unpack2(unsigned long long v) {
    float2 r;
    asm("mov.b64 {%0, %1}, %2;" : "=f"(r.x), "=f"(r.y) : "l"(v));
    return r;
}

template<int LDA>
__device__ __forceinline__ void gemm64x256p(
    const float* __restrict__ A, int K,
    const float* __restrict__ Wg, float* __restrict__ Ws0, float* __restrict__ Ws1,
    unsigned long long (&acc)[8][4], int ty, int tx, int tid)
{
#pragma unroll
    for (int mi = 0; mi < 8; mi++)
#pragma unroll
        for (int ni = 0; ni < 4; ni++) acc[mi][ni] = 0ull;

    const float* Abase = A + ty * 8 * LDA;
    const int ntiles = (K + 31) >> 5;
    const int tx4 = tx << 2;

    float4 pf[8];
    int pr[8], pc[8];
#pragma unroll
    for (int i = 0; i < 8; i++) {
        int f4 = i * 256 + tid;
        pr[i] = f4 >> 6;
        pc[i] = (f4 & 63) << 2;
    }
#pragma unroll
    for (int i = 0; i < 8; i++) {
        int k = pr[i];
        pf[i] = (k < K) ? *(const float4*)&Wg[(size_t)k * 256 + pc[i]]
                        : make_float4(0.f, 0.f, 0.f, 0.f);
    }
    __syncthreads();

    for (int t = 0; t < ntiles; t++) {
        float* Ws = (t & 1) ? Ws1 : Ws0;
#pragma unroll
        for (int i = 0; i < 8; i++)
            *(float4*)&Ws[pr[i] * 256 + pc[i]] = pf[i];
        __syncthreads();
        if (t + 1 < ntiles) {
            int kt = (t + 1) << 5;
#pragma unroll
            for (int i = 0; i < 8; i++) {
                int k = kt + pr[i];
                pf[i] = (k < K) ? *(const float4*)&Wg[(size_t)k * 256 + pc[i]]
                                : make_float4(0.f, 0.f, 0.f, 0.f);
            }
        }
        int kt = t << 5;
        int kc = min(32, K - kt);
        const float* Ap = Abase + kt;
        for (int k = 0; k < kc; k += 2) {
            float2 a01[8];
#pragma unroll
            for (int mi = 0; mi < 8; mi++)
                a01[mi] = *(const float2*)&Ap[mi * LDA + k];
#pragma unroll
            for (int kk = 0; kk < 2; kk++) {
                const float* wrow = &Ws[(k + kk) * 256];
                ulonglong2 bb0 = *(const ulonglong2*)&wrow[tx4];
                ulonglong2 bb1 = *(const ulonglong2*)&wrow[128 + tx4];
#pragma unroll
                for (int mi = 0; mi < 8; mi++) {
                    unsigned long long a2 = dup2(kk ? a01[mi].y : a01[mi].x);
                    FMA2(acc[mi][0], a2, bb0.x);
                    FMA2(acc[mi][1], a2, bb0.y);
                    FMA2(acc[mi][2], a2, bb1.x);
                    FMA2(acc[mi][3], a2, bb1.y);
                }
            }
        }
    }
}

// ---------------- kernel 0: pack expert weights to hi/lo bf16 pairs ----------------
__global__ void wconv_kernel(const float* __restrict__ eW1, const float* __restrict__ eW2,
                             const float* __restrict__ eW3)
{
    int i = blockIdx.x * blockDim.x + threadIdx.x;
    if (i < NE * HD * 168) {
        int p = i % 168; int en = i / 168; int n = en % HD; int e = en / HD;
        size_t kb = ((size_t)e * IND + 2 * p) * HD + n;
        w1p[i] = pack_u64(eW1[kb], eW1[kb + HD]);
    }
    if (i < NE * HD * 128) {
        int p = i % 128; int en = i / 128; int n = en % HD; int e = en / HD;
        size_t kb = ((size_t)e * HD + 2 * p) * HD + n;
        w2p[i] = pack_u64(eW2[kb], eW2[kb + HD]);
        w3p[i] = pack_u64(eW3[kb], eW3[kb + HD]);
    }
}

// ---------------- kernel 1: per-row prep ----------------
__global__ void prep_kernel(
    const float* __restrict__ x, const float* __restrict__ sigma,
    const float* __restrict__ state,
    const float* __restrict__ tW1, const float* __restrict__ tb1,
    const float* __restrict__ tW2, const float* __restrict__ tb2)
{
    if (blockIdx.x == 0 && threadIdx.x < NE) g_count[threadIdx.x] = 0;
    if (blockIdx.x == 0 && threadIdx.x == NE) g_entropy = 0.f;

    int wid  = (blockIdx.x * blockDim.x + threadIdx.x) >> 5;
    int lane = threadIdx.x & 31;
    if (wid >= NB) return;
    int r = wid;

    float sg  = __ldg(&sigma[r]);
    float sd2 = 0.25f;
    float d   = sg - 0.002f;
    float cskip = sd2 / (d * d + sd2);
    float inv = rsqrtf(sg * sg + sd2);
    float cout = d * 0.5f * inv;
    float cin  = inv;
    float rt   = 250.0f * logf(sg + 1e-44f);

    const float FR[8] = { 1.0f, 0.26826957952797246f, 0.07196856730011519f,
                          0.019306977288832496f, 0.005179474679231212f,
                          0.0013894954943731375f, 0.00037275937203149404f,
                          0.0001f };
    float pe[16];
#pragma unroll
    for (int i = 0; i < 8; i++) {
        float s, c;
        sincosf(rt * FR[i], &s, &c);
        pe[i] = s; pe[i + 8] = c;
    }
    float h1 = __ldg(&tb1[lane]);
#pragma unroll
    for (int i = 0; i < 16; i++) h1 = fmaf(pe[i], __ldg(&tW1[i * 32 + lane]), h1);
    {
        float sp = (h1 > 20.f) ? h1 : log1pf(expf(h1));
        h1 = h1 * tanhf(sp);
    }
    float tacc = (lane < 16) ? __ldg(&tb2[lane]) : 0.f;
#pragma unroll
    for (int j = 0; j < 32; j++) {
        float hj = __shfl_sync(0xffffffffu, h1, j);
        if (lane < 16) tacc = fmaf(hj, __ldg(&tW2[j * 16 + lane]), tacc);
    }
    float* row = g_inp + (size_t)r * IND;
    row[lane]      = cin * __ldg(&x[r * 64 + lane]);
    row[32 + lane] = cin * __ldg(&x[r * 64 + 32 + lane]);
    if (lane < 16) row[64 + lane] = tacc;
#pragma unroll
    for (int i = 0; i < 8; i++)
        row[80 + lane + i * 32] = __ldg(&state[r * 256 + lane + i * 32]);
    if (lane == 0) { g_cskip[r] = cskip; g_cout[r] = cout; }
}

// ---------------- kernel 2: gate + softmax + top4 + routing ----------------
__global__ void __launch_bounds__(256, 1) gate_kernel(
    const float* __restrict__ gW1, const float* __restrict__ gb1,
    const float* __restrict__ gW2, const float* __restrict__ gb2)
{
    extern __shared__ float smem[];
    float* Xs   = smem;                  // 64*340
    float* G1   = Xs + 64 * 340;         // 64*260
    float* Ws0  = G1 + 64 * 260;         // 32*256
    float* Ws1  = Ws0 + 32 * 256;        // 32*256
    float* entA = Ws1 + 32 * 256;        // 1

    int tid = threadIdx.x, ty = tid >> 5, tx = tid & 31;
    int base = blockIdx.x * 64;
    if (tid == 0) *entA = 0.f;
#pragma unroll
    for (int rr = 0; rr < 8; rr++) {
        int m = ty * 8 + rr;
        const float* src = g_inp + (size_t)(base + m) * IND;
        for (int k = tx; k < IND; k += 32) Xs[m * 340 + k] = src[k];
    }
    unsigned long long acc[8][4];
    gemm64x256p<340>(Xs, IND, gW1, Ws0, Ws1, acc, ty, tx, tid);
    {
        const int tx4 = tx << 2;
        float bs[8];
#pragma unroll
        for (int i = 0; i < 4; i++) { bs[i] = __ldg(&gb1[tx4 + i]); bs[4 + i] = __ldg(&gb1[128 + tx4 + i]); }
#pragma unroll
        for (int mi = 0; mi < 8; mi++) {
            float* o = G1 + (ty * 8 + mi) * 260;
            float2 p0 = unpack2(acc[mi][0]);
            float2 p1 = unpack2(acc[mi][1]);
            float2 p2 = unpack2(acc[mi][2]);
            float2 p3 = unpack2(acc[mi][3]);
            float4 v0, v1;
            v0.x = fmaxf(p0.x + bs[0], 0.f); v0.y = fmaxf(p0.y + bs[1], 0.f);
            v0.z = fmaxf(p1.x + bs[2], 0.f); v0.w = fmaxf(p1.y + bs[3], 0.f);
            v1.x = fmaxf(p2.x + bs[4], 0.f); v1.y = fmaxf(p2.y + bs[5], 0.f);
            v1.z = fmaxf(p3.x + bs[6], 0.f); v1.w = fmaxf(p3.y + bs[7], 0.f);
            *(float4*)&o[tx4]       = v0;
            *(float4*)&o[128 + tx4] = v1;
        }
    }
    __syncthreads();

    float* W2s = Ws0;
    for (int i = tid; i < 4096; i += 256) W2s[i] = gW2[i];
    __syncthreads();

    int j = tx & 15, kh = tx >> 4;
    for (int rr = 0; rr < 8; rr++) {
        int m = ty * 8 + rr;
        int row = base + m;
        const float* g1 = &G1[m * 260];
        float s = 0.f;
        int k0 = kh * 128;
#pragma unroll 4
        for (int k = 0; k < 128; k++) s = fmaf(g1[k0 + k], W2s[(k0 + k) * 16 + j], s);
        s += __shfl_down_sync(0xffffffffu, s, 16);
        float gv = s + __ldg(&gb2[j]);
        float p[16];
#pragma unroll
        for (int q = 0; q < 16; q++) p[q] = __shfl_sync(0xffffffffu, gv, q);
        float mx = p[0];
#pragma unroll
        for (int q = 1; q < 16; q++) mx = fmaxf(mx, p[q]);
        float Z = 0.f;
#pragma unroll
        for (int q = 0; q < 16; q++) { p[q] = expf(p[q] - mx); Z += p[q]; }
        float invZ = 1.f / Z;
        float ent = 0.f;
#pragma unroll
        for (int q = 0; q < 16; q++) { p[q] *= invZ; ent -= p[q] * logf(p[q] + 1e-9f); }
        unsigned usedm = 0;
        int   idx[4]; float val[4]; float wsum = 0.f;
#pragma unroll
        for (int s4 = 0; s4 < 4; s4++) {
            int best = 0; float bv = -1.f;
#pragma unroll
            for (int q = 0; q < 16; q++) {
                bool free = !((usedm >> q) & 1u);
                if (free && p[q] > bv) { bv = p[q]; best = q; }
            }
            usedm |= (1u << best);
            idx[s4] = best; val[s4] = bv; wsum += bv;
        }
        float invw = 1.f / (wsum + 1e-9f);
        if (tx < 4) {
            int ee = idx[tx];
            int pos = atomicAdd(&g_count[ee], 1);
            g_bucket[ee * NB + pos] = row | (tx << 16);
            g_bw[ee * NB + pos] = val[tx] * invw;
        }
        if (tx == 0) atomicAdd(entA, ent);
    }
    __syncthreads();
    if (tid == 0) atomicAdd(&g_entropy, *entA);
}

// ---------------- kernel 3: bf16-split HMMA routed 3-layer expert MLP ----------------
// SMEM byte layout:
#define LDPA0 169
#define LDPA1 129
#define LDPW  18
#define XSM_A0   0                       // 64*169*8 = 86528
#define XSM_A1   86528                   // 64*129*8 = 66048
#define XSM_W    152576                  // 2 * 256*18*8 = 73728
#define XSM_META 226304                  // srow(256) swt(256) sb1/2/3(3*1024) = 3584
#define XSM_TOTAL 229888

__global__ void __launch_bounds__(256, 1) expert_kernel(
    const float* __restrict__ eb1, const float* __restrict__ eb2,
    const float* __restrict__ eb3)
{
    extern __shared__ char sm[];
    int e = blockIdx.y;
    int cnt = g_count[e];
    int base = blockIdx.x * 64;
    if (base >= cnt) return;

    int tid = threadIdx.x;
    int lane = tid & 31, wid = tid >> 5;
    int wm = wid >> 2, wn = wid & 3;       // warp tile: rows [wm*32,+32), cols [wn*64,+64)
    int g = lane >> 2, t = lane & 3;

    int*   srow = (int*)(sm + XSM_META);
    float* swt  = (float*)(sm + XSM_META + 256);
    float* sb1  = (float*)(sm + XSM_META + 512);
    float* sb2  = (float*)(sm + XSM_META + 1536);
    float* sb3  = (float*)(sm + XSM_META + 2560);

    if (tid < 64) {
        int gi = base + tid;
        int gj = (gi < cnt) ? gi : (cnt - 1);
        srow[tid] = g_bucket[e * NB + gj];
        swt[tid]  = (gi < cnt) ? g_bw[e * NB + gj] : 0.f;
    }
    sb1[tid] = eb1[e * HD + tid];
    sb2[tid] = eb2[e * HD + tid];
    sb3[tid] = eb3[e * HD + tid];
    __syncthreads();

    // stage layer-1 activations (hi/lo pairs) into A0
    {
        int r = tid & 63, q = tid >> 6;
        int rid = srow[r] & 0xFFFF;
        const float2* src = (const float2*)(g_inp + (size_t)rid * IND);
        uint2* A0 = (uint2*)(sm + XSM_A0);
        for (int p = q * 42; p < q * 42 + 42; p++) {
            float2 v = src[p];
            A0[r * LDPA0 + p] = pack2(v.x, v.y);
        }
    }

    uint32_t smb = smem_u32(sm);
    float c[2][8][4];

    const unsigned long long* wg1 = w1p + (size_t)e * HD * 168;
    const unsigned long long* wg2 = w2p + (size_t)e * HD * 128;
    const unsigned long long* wg3 = w3p + (size_t)e * HD * 128;

    auto run_layer = [&](const unsigned long long* wg, int PKP, int Abase, int LDPA) {
#pragma unroll
        for (int a = 0; a < 2; a++)
#pragma unroll
            for (int b = 0; b < 8; b++)
#pragma unroll
                for (int d = 0; d < 4; d++) c[a][b][d] = 0.f;
        int nch = (PKP + 15) >> 4;
        __syncthreads();   // prior phase (A writes / W reads) fully done
        {   // prefill chunk 0 -> buf 0
            int pc = min(16, PKP);
            const unsigned long long* src = wg + (size_t)tid * PKP;
            uint32_t dst = smb + XSM_W + tid * (LDPW * 8);
            for (int i = 0; i < (pc >> 1); i++) cpasync16(dst + i * 16, src + i * 2);
            CP_COMMIT();
        }
        for (int ch = 0; ch < nch; ch++) {
            CP_WAIT0();
            __syncthreads();
            if (ch + 1 < nch) {
                int pc = min(16, PKP - (ch + 1) * 16);
                const unsigned long long* src = wg + (size_t)tid * PKP + (ch + 1) * 16;
                uint32_t dst = smb + XSM_W + ((ch + 1) & 1) * 36864 + tid * (LDPW * 8);
                for (int i = 0; i < (pc >> 1); i++) cpasync16(dst + i * 16, src + i * 2);
                CP_COMMIT();
            }
            int ksteps = min(16, PKP - ch * 16) >> 3;
            const uint2* A = (const uint2*)(sm + Abase);
            const uint2* W = (const uint2*)(sm + XSM_W + (ch & 1) * 36864);
            for (int ks = 0; ks < ksteps; ks++) {
                int po = ch * 16 + ks * 8;
                uint32_t ah[2][4], al[2][4];
#pragma unroll
                for (int mt = 0; mt < 2; mt++) {
                    int row = wm * 32 + mt * 16 + g;
                    uint2 v0 = A[row * LDPA + po + t];
                    uint2 v1 = A[(row + 8) * LDPA + po + t];
                    uint2 v2 = A[row * LDPA + po + t + 4];
                    uint2 v3 = A[(row + 8) * LDPA + po + t + 4];
                    ah[mt][0] = v0.x; al[mt][0] = v0.y;
                    ah[mt][1] = v1.x; al[mt][1] = v1.y;
                    ah[mt][2] = v2.x; al[mt][2] = v2.y;
                    ah[mt][3] = v3.x; al[mt][3] = v3.y;
                }
#pragma unroll
                for (int nt = 0; nt < 8; nt++) {
                    int n = wn * 64 + nt * 8 + g;
                    uint2 b0 = W[n * LDPW + ks * 8 + t];
                    uint2 b1 = W[n * LDPW + ks * 8 + t + 4];
#pragma unroll
                    for (int mt = 0; mt < 2; mt++) {
                        mma_bf16(c[mt][nt], ah[mt], b0.x, b1.x);   // hi*hi
                        mma_bf16(c[mt][nt], ah[mt], b0.y, b1.y);   // hi*lo
                        mma_bf16(c[mt][nt], al[mt], b0.x, b1.x);   // lo*hi
                    }
                }
            }
        }
    };

    auto write_act = [&](const float* sb, int Abase, int LDPA) {
        uint2* An = (uint2*)(sm + Abase);
#pragma unroll
        for (int mt = 0; mt < 2; mt++) {
            int row0 = wm * 32 + mt * 16 + g;
#pragma unroll
            for (int nt = 0; nt < 8; nt++) {
                int col = wn * 64 + nt * 8 + 2 * t;
                float b0 = sb[col], b1 = sb[col + 1];
                int p = wn * 32 + nt * 4 + t;
                An[row0 * LDPA + p]       = pack2(mishf(c[mt][nt][0] + b0), mishf(c[mt][nt][1] + b1));
                An[(row0 + 8) * LDPA + p] = pack2(mishf(c[mt][nt][2] + b0), mishf(c[mt][nt][3] + b1));
            }
        }
    };

    run_layer(wg1, 168, XSM_A0, LDPA0);
    write_act(sb1, XSM_A1, LDPA1);
    run_layer(wg2, 128, XSM_A1, LDPA1);
    write_act(sb2, XSM_A0, LDPA0);
    run_layer(wg3, 128, XSM_A0, LDPA0);

    // epilogue: g_eout[row*4+slot][col] = w * mish(C + b3)
#pragma unroll
    for (int mt = 0; mt < 2; mt++) {
#pragma unroll
        for (int half = 0; half < 2; half++) {
            int m = wm * 32 + mt * 16 + half * 8 + g;
            int gi = base + m;
            if (gi < cnt) {
                int packed = srow[m];
                int row = packed & 0xFFFF, slot = packed >> 16;
                float w = swt[m];
                float* dst = g_eout + ((size_t)(row * 4 + slot)) * HD;
#pragma unroll
                for (int nt = 0; nt < 8; nt++) {
                    int col = wn * 64 + nt * 8 + 2 * t;
                    float2 o;
                    o.x = w * mishf(c[mt][nt][half * 2 + 0] + sb3[col]);
                    o.y = w * mishf(c[mt][nt][half * 2 + 1] + sb3[col + 1]);
                    *(float2*)&dst[col] = o;
                }
            }
        }
    }
}

// ---------------- kernel 4: combine slots + final linear + epilogue ----------------
__global__ void __launch_bounds__(256, 1) final_kernel(
    const float* __restrict__ x, const float* __restrict__ fW,
    const float* __restrict__ fb, float* __restrict__ out)
{
    extern __shared__ float smem[];
    float* cs  = smem;             // 64*260
    float* fWs = cs + 64 * 260;    // 256*64
    int tid = threadIdx.x;
    int base = blockIdx.x * 64;

    for (int i = tid; i < 4096; i += 256)
        ((float4*)fWs)[i] = ((const float4*)fW)[i];
    for (int idx = tid; idx < 64 * 64; idx += 256) {
        int m = idx >> 6, n4 = (idx & 63) << 2;
        size_t rb = ((size_t)(base + m)) * 4 * HD + n4;
        float4 a = *(const float4*)&g_eout[rb];
        float4 b = *(const float4*)&g_eout[rb + 256];
        float4 c = *(const float4*)&g_eout[rb + 512];
        float4 d = *(const float4*)&g_eout[rb + 768];
        float4 v;
        v.x = a.x + b.x + c.x + d.x;
        v.y = a.y + b.y + c.y + d.y;
        v.z = a.z + b.z + c.z + d.z;
        v.w = a.w + b.w + c.w + d.w;
        *(float4*)&cs[m * 260 + n4] = v;
    }
    __syncthreads();

    int ty = tid >> 4, tx = tid & 15;
    float acc[4][4];
#pragma unroll
    for (int mi = 0; mi < 4; mi++)
#pragma unroll
        for (int ci = 0; ci < 4; ci++) acc[mi][ci] = 0.f;
#pragma unroll 4
    for (int k = 0; k < 256; k++) {
        float4 b = *(const float4*)&fWs[k * 64 + (tx << 2)];
#pragma unroll
        for (int mi = 0; mi < 4; mi++) {
            float a = cs[(ty * 4 + mi) * 260 + k];
            acc[mi][0] = fmaf(a, b.x, acc[mi][0]);
            acc[mi][1] = fmaf(a, b.y, acc[mi][1]);
            acc[mi][2] = fmaf(a, b.z, acc[mi][2]);
            acc[mi][3] = fmaf(a, b.w, acc[mi][3]);
        }
    }
#pragma unroll
    for (int mi = 0; mi < 4; mi++) {
        int row = base + ty * 4 + mi;
        float co = g_cout[row], ck = g_cskip[row];
        float4 xr = *(const float4*)&x[row * 64 + (tx << 2)];
        float4 o;
        o.x = fminf(fmaxf(co * (acc[mi][0] + __ldg(&fb[(tx << 2) + 0])) + ck * xr.x, -1.f), 1.f);
        o.y = fminf(fmaxf(co * (acc[mi][1] + __ldg(&fb[(tx << 2) + 1])) + ck * xr.y, -1.f), 1.f);
        o.z = fminf(fmaxf(co * (acc[mi][2] + __ldg(&fb[(tx << 2) + 2])) + ck * xr.z, -1.f), 1.f);
        o.w = fminf(fmaxf(co * (acc[mi][3] + __ldg(&fb[(tx << 2) + 3])) + ck * xr.w, -1.f), 1.f);
        *(float4*)&out[row * 64 + (tx << 2)] = o;
    }
}

// ---------------- kernel 5: aux loss ----------------
__global__ void aux_kernel(float* __restrict__ out, int out_size)
{
    if (threadIdx.x == 0 && out_size > NB * NACT) {
        float load[NE], mean = 0.f;
#pragma unroll
        for (int e = 0; e < NE; e++) { load[e] = (float)g_count[e] / (32768.0f + 1e-9f); mean += load[e]; }
        mean *= (1.0f / NE);
        float var = 0.f;
#pragma unroll
        for (int e = 0; e < NE; e++) { float d = load[e] - mean; var += d * d; }
        var *= (1.0f / (NE - 1));
        out[NB * NACT] = var + g_entropy / 32768.0f;
    }
}

extern "C" void kernel_launch(void* const* d_in, const int* in_sizes, int n_in,
                              void* d_out, int out_size)
{
    const float* x     = (const float*)d_in[0];
    const float* sigma = (const float*)d_in[1];
    const float* state = (const float*)d_in[2];
    const float* tW1 = (const float*)d_in[3];
    const float* tb1 = (const float*)d_in[4];
    const float* tW2 = (const float*)d_in[5];
    const float* tb2 = (const float*)d_in[6];
    const float* gW1 = (const float*)d_in[7];
    const float* gb1 = (const float*)d_in[8];
    const float* gW2 = (const float*)d_in[9];
    const float* gb2 = (const float*)d_in[10];
    const float* eW1 = (const float*)d_in[11];
    const float* eb1 = (const float*)d_in[12];
    const float* eW2 = (const float*)d_in[13];
    const float* eb2 = (const float*)d_in[14];
    const float* eW3 = (const float*)d_in[15];
    const float* eb3 = (const float*)d_in[16];
    const float* fW  = (const float*)d_in[17];
    const float* fb  = (const float*)d_in[18];
    float* out = (float*)d_out;

    const int gateSmem = (64 * 340 + 64 * 260 + 2 * 32 * 256 + 16) * 4;
    const int finSmem  = (64 * 260 + 256 * 64 + 16) * 4;
    cudaFuncSetAttribute(gate_kernel,   cudaFuncAttributeMaxDynamicSharedMemorySize, gateSmem);
    cudaFuncSetAttribute(expert_kernel, cudaFuncAttributeMaxDynamicSharedMemorySize, XSM_TOTAL);
    cudaFuncSetAttribute(final_kernel,  cudaFuncAttributeMaxDynamicSharedMemorySize, finSmem);

    prep_kernel<<<NB / 8, 256>>>(x, sigma, state, tW1, tb1, tW2, tb2);
    wconv_kernel<<<(NE * HD * 168 + 255) / 256, 256>>>(eW1, eW2, eW3);
    gate_kernel<<<NB / 64, 256, gateSmem>>>(gW1, gb1, gW2, gb2);
    expert_kernel<<<dim3(NB / 64, NE), 256, XSM_TOTAL>>>(eb1, eb2, eb3);
    final_kernel<<<NB / 64, 256, finSmem>>>(x, fW, fb, out);
    aux_kernel<<<1, 32>>>(out, out_size);
}

// round 7
// speedup vs baseline: 1.9514x; 1.4105x over previous
#include <cuda_runtime.h>
#include <cuda_bf16.h>
#include <math.h>
#include <stdint.h>

#define NB   32768
#define IND  336
#define HD   256
#define NE   16
#define NACT 64

// ---------------- device scratch ----------------
__device__ float g_inp[(size_t)NB * IND];
__device__ float g_cskip[NB];
__device__ float g_cout[NB];
__device__ int   g_count[NE];
__device__ float g_entropy;
__device__ int   g_bucket[NE * NB];             // row | slot<<16
__device__ float g_bw[NE * NB];
__device__ float g_eout[(size_t)NB * 4 * HD];   // per-(row,slot) weighted expert out

// packed weights [e][pair][n]: u64 = {hi(2k),hi(2k+1),lo(2k),lo(2k+1)}
__device__ __align__(16) unsigned long long w1p[NE * 168 * HD];
__device__ __align__(16) unsigned long long w2p[NE * 128 * HD];
__device__ __align__(16) unsigned long long w3p[NE * 128 * HD];

__device__ __forceinline__ float mishf(float v) {
    if (v > 20.f) return v;
    float u = __expf(v);
    float w = 1.f + u;
    w = w * w;
    return v * __fdividef(w - 1.f, w + 1.f);
}

// ---------------- packing helpers ----------------
__device__ __forceinline__ uint2 pack2(float a, float b) {
    __nv_bfloat16 ha = __float2bfloat16_rn(a), hb = __float2bfloat16_rn(b);
    __nv_bfloat16 la = __float2bfloat16_rn(a - __bfloat162float(ha));
    __nv_bfloat16 lb = __float2bfloat16_rn(b - __bfloat162float(hb));
    uint2 r;
    r.x = (uint32_t)*(unsigned short*)&ha | ((uint32_t)*(unsigned short*)&hb << 16);
    r.y = (uint32_t)*(unsigned short*)&la | ((uint32_t)*(unsigned short*)&lb << 16);
    return r;
}
__device__ __forceinline__ unsigned long long pack_u64(float a, float b) {
    uint2 r = pack2(a, b);
    return (unsigned long long)r.x | ((unsigned long long)r.y << 32);
}

// ---------------- mma.sync / cp.async (baseline PTX) ----------------
__device__ __forceinline__ void mma_bf16(float* c, const uint32_t* a, uint32_t b0, uint32_t b1) {
    asm volatile(
        "mma.sync.aligned.m16n8k16.row.col.f32.bf16.bf16.f32 "
        "{%0,%1,%2,%3}, {%4,%5,%6,%7}, {%8,%9}, {%0,%1,%2,%3};"
        : "+f"(c[0]), "+f"(c[1]), "+f"(c[2]), "+f"(c[3])
        : "r"(a[0]), "r"(a[1]), "r"(a[2]), "r"(a[3]), "r"(b0), "r"(b1));
}
__device__ __forceinline__ uint32_t smem_u32(const void* p) {
    uint32_t a;
    asm("{ .reg .u64 t; cvta.to.shared.u64 t, %1; cvt.u32.u64 %0, t; }" : "=r"(a) : "l"(p));
    return a;
}
__device__ __forceinline__ void cpasync16(uint32_t dst, const void* src) {
    asm volatile("cp.async.cg.shared.global [%0], [%1], 16;" :: "r"(dst), "l"(src) : "memory");
}
#define CP_COMMIT() asm volatile("cp.async.commit_group;" ::: "memory")
#define CP_WAIT0()  asm volatile("cp.async.wait_group 0;" ::: "memory")
#define CP_WAIT1()  asm volatile("cp.async.wait_group 1;" ::: "memory")

// ---------------- packed fp32x2 FMA machinery (gate kernel) ----------------
#define FMA2(d, a, b) asm("fma.rn.f32x2 %0, %1, %2, %0;" : "+l"(d) : "l"(a), "l"(b))
__device__ __forceinline__ unsigned long long dup2(float v) {
    unsigned long long r;
    asm("mov.b64 %0, {%1, %1};" : "=l"(r) : "r"(__float_as_uint(v)));
    return r;
}
__device__ __forceinline__ float2 unpack2(unsigned long long v) {
    float2 r;
    asm("mov.b64 {%0, %1}, %2;" : "=f"(r.x), "=f"(r.y) : "l"(v));
    return r;
}

template<int LDA>
__device__ __forceinline__ void gemm64x256p(
    const float* __restrict__ A, int K,
    const float* __restrict__ Wg, float* __restrict__ Ws0, float* __restrict__ Ws1,
    unsigned long long (&acc)[8][4], int ty, int tx, int tid)
{
#pragma unroll
    for (int mi = 0; mi < 8; mi++)
#pragma unroll
        for (int ni = 0; ni < 4; ni++) acc[mi][ni] = 0ull;

    const float* Abase = A + ty * 8 * LDA;
    const int ntiles = (K + 31) >> 5;
    const int tx4 = tx << 2;

    float4 pf[8];
    int pr[8], pc[8];
#pragma unroll
    for (int i = 0; i < 8; i++) {
        int f4 = i * 256 + tid;
        pr[i] = f4 >> 6;
        pc[i] = (f4 & 63) << 2;
    }
#pragma unroll
    for (int i = 0; i < 8; i++) {
        int k = pr[i];
        pf[i] = (k < K) ? *(const float4*)&Wg[(size_t)k * 256 + pc[i]]
                        : make_float4(0.f, 0.f, 0.f, 0.f);
    }
    __syncthreads();

    for (int t = 0; t < ntiles; t++) {
        float* Ws = (t & 1) ? Ws1 : Ws0;
#pragma unroll
        for (int i = 0; i < 8; i++)
            *(float4*)&Ws[pr[i] * 256 + pc[i]] = pf[i];
        __syncthreads();
        if (t + 1 < ntiles) {
            int kt = (t + 1) << 5;
#pragma unroll
            for (int i = 0; i < 8; i++) {
                int k = kt + pr[i];
                pf[i] = (k < K) ? *(const float4*)&Wg[(size_t)k * 256 + pc[i]]
                                : make_float4(0.f, 0.f, 0.f, 0.f);
            }
        }
        int kt = t << 5;
        int kc = min(32, K - kt);
        const float* Ap = Abase + kt;
        for (int k = 0; k < kc; k += 2) {
            float2 a01[8];
#pragma unroll
            for (int mi = 0; mi < 8; mi++)
                a01[mi] = *(const float2*)&Ap[mi * LDA + k];
#pragma unroll
            for (int kk = 0; kk < 2; kk++) {
                const float* wrow = &Ws[(k + kk) * 256];
                ulonglong2 bb0 = *(const ulonglong2*)&wrow[tx4];
                ulonglong2 bb1 = *(const ulonglong2*)&wrow[128 + tx4];
#pragma unroll
                for (int mi = 0; mi < 8; mi++) {
                    unsigned long long a2 = dup2(kk ? a01[mi].y : a01[mi].x);
                    FMA2(acc[mi][0], a2, bb0.x);
                    FMA2(acc[mi][1], a2, bb0.y);
                    FMA2(acc[mi][2], a2, bb1.x);
                    FMA2(acc[mi][3], a2, bb1.y);
                }
            }
        }
    }
}

// ---------------- kernel 0: pack expert weights to [e][pair][n] ----------------
__global__ void wconv_kernel(const float* __restrict__ eW1, const float* __restrict__ eW2,
                             const float* __restrict__ eW3)
{
    int i = blockIdx.x * blockDim.x + threadIdx.x;
    if (i < NE * 168 * HD) {
        int n = i & 255; int pn = i >> 8; int p = pn % 168; int e = pn / 168;
        size_t kb = ((size_t)e * IND + 2 * p) * HD + n;
        w1p[i] = pack_u64(eW1[kb], eW1[kb + HD]);
    }
    if (i < NE * 128 * HD) {
        int n = i & 255; int pn = i >> 8; int p = pn % 128; int e = pn / 128;
        size_t kb = ((size_t)e * HD + 2 * p) * HD + n;
        w2p[i] = pack_u64(eW2[kb], eW2[kb + HD]);
        w3p[i] = pack_u64(eW3[kb], eW3[kb + HD]);
    }
}

// ---------------- kernel 1: per-row prep ----------------
__global__ void prep_kernel(
    const float* __restrict__ x, const float* __restrict__ sigma,
    const float* __restrict__ state,
    const float* __restrict__ tW1, const float* __restrict__ tb1,
    const float* __restrict__ tW2, const float* __restrict__ tb2)
{
    if (blockIdx.x == 0 && threadIdx.x < NE) g_count[threadIdx.x] = 0;
    if (blockIdx.x == 0 && threadIdx.x == NE) g_entropy = 0.f;

    int wid  = (blockIdx.x * blockDim.x + threadIdx.x) >> 5;
    int lane = threadIdx.x & 31;
    if (wid >= NB) return;
    int r = wid;

    float sg  = __ldg(&sigma[r]);
    float sd2 = 0.25f;
    float d   = sg - 0.002f;
    float cskip = sd2 / (d * d + sd2);
    float inv = rsqrtf(sg * sg + sd2);
    float cout = d * 0.5f * inv;
    float cin  = inv;
    float rt   = 250.0f * logf(sg + 1e-44f);

    const float FR[8] = { 1.0f, 0.26826957952797246f, 0.07196856730011519f,
                          0.019306977288832496f, 0.005179474679231212f,
                          0.0013894954943731375f, 0.00037275937203149404f,
                          0.0001f };
    float pe[16];
#pragma unroll
    for (int i = 0; i < 8; i++) {
        float s, c;
        sincosf(rt * FR[i], &s, &c);
        pe[i] = s; pe[i + 8] = c;
    }
    float h1 = __ldg(&tb1[lane]);
#pragma unroll
    for (int i = 0; i < 16; i++) h1 = fmaf(pe[i], __ldg(&tW1[i * 32 + lane]), h1);
    {
        float sp = (h1 > 20.f) ? h1 : log1pf(expf(h1));
        h1 = h1 * tanhf(sp);
    }
    float tacc = (lane < 16) ? __ldg(&tb2[lane]) : 0.f;
#pragma unroll
    for (int j = 0; j < 32; j++) {
        float hj = __shfl_sync(0xffffffffu, h1, j);
        if (lane < 16) tacc = fmaf(hj, __ldg(&tW2[j * 16 + lane]), tacc);
    }
    float* row = g_inp + (size_t)r * IND;
    row[lane]      = cin * __ldg(&x[r * 64 + lane]);
    row[32 + lane] = cin * __ldg(&x[r * 64 + 32 + lane]);
    if (lane < 16) row[64 + lane] = tacc;
#pragma unroll
    for (int i = 0; i < 8; i++)
        row[80 + lane + i * 32] = __ldg(&state[r * 256 + lane + i * 32]);
    if (lane == 0) { g_cskip[r] = cskip; g_cout[r] = cout; }
}

// ---------------- kernel 2: gate + softmax + top4 + routing ----------------
__global__ void __launch_bounds__(256, 1) gate_kernel(
    const float* __restrict__ gW1, const float* __restrict__ gb1,
    const float* __restrict__ gW2, const float* __restrict__ gb2)
{
    extern __shared__ float smem[];
    float* Xs   = smem;                  // 64*340
    float* G1   = Xs + 64 * 340;         // 64*260
    float* Ws0  = G1 + 64 * 260;         // 32*256
    float* Ws1  = Ws0 + 32 * 256;        // 32*256
    float* entA = Ws1 + 32 * 256;        // 1

    int tid = threadIdx.x, ty = tid >> 5, tx = tid & 31;
    int base = blockIdx.x * 64;
    if (tid == 0) *entA = 0.f;
#pragma unroll
    for (int rr = 0; rr < 8; rr++) {
        int m = ty * 8 + rr;
        const float* src = g_inp + (size_t)(base + m) * IND;
        for (int k = tx; k < IND; k += 32) Xs[m * 340 + k] = src[k];
    }
    unsigned long long acc[8][4];
    gemm64x256p<340>(Xs, IND, gW1, Ws0, Ws1, acc, ty, tx, tid);
    {
        const int tx4 = tx << 2;
        float bs[8];
#pragma unroll
        for (int i = 0; i < 4; i++) { bs[i] = __ldg(&gb1[tx4 + i]); bs[4 + i] = __ldg(&gb1[128 + tx4 + i]); }
#pragma unroll
        for (int mi = 0; mi < 8; mi++) {
            float* o = G1 + (ty * 8 + mi) * 260;
            float2 p0 = unpack2(acc[mi][0]);
            float2 p1 = unpack2(acc[mi][1]);
            float2 p2 = unpack2(acc[mi][2]);
            float2 p3 = unpack2(acc[mi][3]);
            float4 v0, v1;
            v0.x = fmaxf(p0.x + bs[0], 0.f); v0.y = fmaxf(p0.y + bs[1], 0.f);
            v0.z = fmaxf(p1.x + bs[2], 0.f); v0.w = fmaxf(p1.y + bs[3], 0.f);
            v1.x = fmaxf(p2.x + bs[4], 0.f); v1.y = fmaxf(p2.y + bs[5], 0.f);
            v1.z = fmaxf(p3.x + bs[6], 0.f); v1.w = fmaxf(p3.y + bs[7], 0.f);
            *(float4*)&o[tx4]       = v0;
            *(float4*)&o[128 + tx4] = v1;
        }
    }
    __syncthreads();

    float* W2s = Ws0;
    for (int i = tid; i < 4096; i += 256) W2s[i] = gW2[i];
    __syncthreads();

    int j = tx & 15, kh = tx >> 4;
    for (int rr = 0; rr < 8; rr++) {
        int m = ty * 8 + rr;
        int row = base + m;
        const float* g1 = &G1[m * 260];
        float s = 0.f;
        int k0 = kh * 128;
#pragma unroll 4
        for (int k = 0; k < 128; k++) s = fmaf(g1[k0 + k], W2s[(k0 + k) * 16 + j], s);
        s += __shfl_down_sync(0xffffffffu, s, 16);
        float gv = s + __ldg(&gb2[j]);
        float p[16];
#pragma unroll
        for (int q = 0; q < 16; q++) p[q] = __shfl_sync(0xffffffffu, gv, q);
        float mx = p[0];
#pragma unroll
        for (int q = 1; q < 16; q++) mx = fmaxf(mx, p[q]);
        float Z = 0.f;
#pragma unroll
        for (int q = 0; q < 16; q++) { p[q] = expf(p[q] - mx); Z += p[q]; }
        float invZ = 1.f / Z;
        float ent = 0.f;
#pragma unroll
        for (int q = 0; q < 16; q++) { p[q] *= invZ; ent -= p[q] * logf(p[q] + 1e-9f); }
        unsigned usedm = 0;
        int   idx[4]; float val[4]; float wsum = 0.f;
#pragma unroll
        for (int s4 = 0; s4 < 4; s4++) {
            int best = 0; float bv = -1.f;
#pragma unroll
            for (int q = 0; q < 16; q++) {
                bool free = !((usedm >> q) & 1u);
                if (free && p[q] > bv) { bv = p[q]; best = q; }
            }
            usedm |= (1u << best);
            idx[s4] = best; val[s4] = bv; wsum += bv;
        }
        float invw = 1.f / (wsum + 1e-9f);
        if (tx < 4) {
            int ee = idx[tx];
            int pos = atomicAdd(&g_count[ee], 1);
            g_bucket[ee * NB + pos] = row | (tx << 16);
            g_bw[ee * NB + pos] = val[tx] * invw;
        }
        if (tx == 0) atomicAdd(entA, ent);
    }
    __syncthreads();
    if (tid == 0) atomicAdd(&g_entropy, *entA);
}

// ---------------- kernel 3: bf16-split HMMA expert MLP (conflict-free, 16 warps) ----------------
// A layout: [pair][row], stride 68 u64 (word-stride 136 ≡ 8 mod 32 → conflict-free frags)
// W layout: [pair][n],  stride 260 u64 (word-stride 520 ≡ 8 mod 32)
#define LDA_U 68
#define LDW_U 260
#define WBUF  (8 * LDW_U * 8)            // 16640 bytes per 8-pair chunk buffer
#define XSM_A0   0                        // 168*68*8 = 91392
#define XSM_A1   91392                    // 128*68*8 = 69632
#define XSM_W    161024                   // 3 * 16640 = 49920
#define XSM_META 210944                   // srow 256 | swt 256 | sb1/2/3 3*1024
#define XSM_TOTAL 214528

__global__ void __launch_bounds__(512, 1) expert_kernel(
    const float* __restrict__ eb1, const float* __restrict__ eb2,
    const float* __restrict__ eb3)
{
    extern __shared__ char sm[];
    int e = blockIdx.y;
    int cnt = g_count[e];
    int base = blockIdx.x * 64;
    if (base >= cnt) return;

    int tid = threadIdx.x;
    int lane = tid & 31, wid = tid >> 5;
    int wm = wid >> 3, wn = wid & 7;       // warp tile: rows [wm*32,+32), cols [wn*32,+32)
    int g = lane >> 2, t = lane & 3;

    int*   srow = (int*)(sm + XSM_META);
    float* swt  = (float*)(sm + XSM_META + 256);
    float* sb1  = (float*)(sm + XSM_META + 512);
    float* sb2  = (float*)(sm + XSM_META + 1536);
    float* sb3  = (float*)(sm + XSM_META + 2560);

    if (tid < 64) {
        int gi = base + tid;
        int gj = (gi < cnt) ? gi : (cnt - 1);
        srow[tid] = g_bucket[e * NB + gj];
        swt[tid]  = (gi < cnt) ? g_bw[e * NB + gj] : 0.f;
    }
    if (tid < 256) {
        sb1[tid] = eb1[e * HD + tid];
        sb2[tid] = eb2[e * HD + tid];
        sb3[tid] = eb3[e * HD + tid];
    }
    __syncthreads();

    // stage layer-1 activations: A0[pair][row]
    {
        int r = tid & 63, q = tid >> 6;           // q in [0,8), 21 pairs each
        int rid = srow[r] & 0xFFFF;
        const float2* src = (const float2*)(g_inp + (size_t)rid * IND);
        uint2* A0 = (uint2*)(sm + XSM_A0);
        for (int p = q * 21; p < q * 21 + 21; p++) {
            float2 v = src[p];
            A0[p * LDA_U + r] = pack2(v.x, v.y);
        }
    }

    uint32_t smb = smem_u32(sm);
    float c[2][4][4];

    const unsigned long long* wg1 = w1p + (size_t)e * 168 * HD;
    const unsigned long long* wg2 = w2p + (size_t)e * 128 * HD;
    const unsigned long long* wg3 = w3p + (size_t)e * 128 * HD;

    auto copy_chunk = [&](const unsigned long long* wg, int ch) {
        uint32_t dstb = smb + XSM_W + (ch % 3) * WBUF;
#pragma unroll
        for (int j = 0; j < 2; j++) {
            int u = tid + j * 512;                 // 1024 x 16B units
            int pl = u >> 7;                       // pair-local 0..7
            int n2 = (u & 127) << 1;               // n, n+1
            const unsigned long long* src = wg + ((size_t)(ch * 8 + pl)) * HD + n2;
            cpasync16(dstb + (pl * LDW_U + n2) * 8, src);
        }
    };

    auto run_layer = [&](const unsigned long long* wg, int PKP, int Abase) {
#pragma unroll
        for (int a = 0; a < 2; a++)
#pragma unroll
            for (int b = 0; b < 4; b++)
#pragma unroll
                for (int d = 0; d < 4; d++) c[a][b][d] = 0.f;
        int nch = PKP >> 3;
        __syncthreads();                           // A ready; prior W reads done
        copy_chunk(wg, 0); CP_COMMIT();
        if (nch > 1) { copy_chunk(wg, 1); CP_COMMIT(); }

        for (int ch = 0; ch < nch; ch++) {
            if (ch + 1 < nch) { CP_WAIT1(); } else { CP_WAIT0(); }
            __syncthreads();
            if (ch + 2 < nch) { copy_chunk(wg, ch + 2); CP_COMMIT(); }

            const uint2* A = (const uint2*)(sm + Abase);
            const uint2* W = (const uint2*)(sm + XSM_W + (ch % 3) * WBUF);
            int po = ch * 8;
            uint32_t ah[2][4], al[2][4];
#pragma unroll
            for (int mt = 0; mt < 2; mt++) {
                int row = wm * 32 + mt * 16 + g;
                uint2 v0 = A[(po + t) * LDA_U + row];
                uint2 v1 = A[(po + t) * LDA_U + row + 8];
                uint2 v2 = A[(po + t + 4) * LDA_U + row];
                uint2 v3 = A[(po + t + 4) * LDA_U + row + 8];
                ah[mt][0] = v0.x; al[mt][0] = v0.y;
                ah[mt][1] = v1.x; al[mt][1] = v1.y;
                ah[mt][2] = v2.x; al[mt][2] = v2.y;
                ah[mt][3] = v3.x; al[mt][3] = v3.y;
            }
#pragma unroll
            for (int nt = 0; nt < 4; nt++) {
                int n = wn * 32 + nt * 8 + g;
                uint2 b0 = W[t * LDW_U + n];
                uint2 b1 = W[(t + 4) * LDW_U + n];
#pragma unroll
                for (int mt = 0; mt < 2; mt++) {
                    mma_bf16(c[mt][nt], ah[mt], b0.x, b1.x);   // hi*hi
                    mma_bf16(c[mt][nt], ah[mt], b0.y, b1.y);   // hi*lo
                    mma_bf16(c[mt][nt], al[mt], b0.x, b1.x);   // lo*hi
                }
            }
        }
    };

    auto write_act = [&](const float* sb, int Abase) {
        uint2* An = (uint2*)(sm + Abase);
#pragma unroll
        for (int mt = 0; mt < 2; mt++) {
            int row0 = wm * 32 + mt * 16 + g;
#pragma unroll
            for (int nt = 0; nt < 4; nt++) {
                int col = wn * 32 + nt * 8 + 2 * t;
                int p = wn * 16 + nt * 4 + t;
                float b0 = sb[col], b1 = sb[col + 1];
                An[p * LDA_U + row0]     = pack2(mishf(c[mt][nt][0] + b0), mishf(c[mt][nt][1] + b1));
                An[p * LDA_U + row0 + 8] = pack2(mishf(c[mt][nt][2] + b0), mishf(c[mt][nt][3] + b1));
            }
        }
    };

    run_layer(wg1, 168, XSM_A0);
    write_act(sb1, XSM_A1);
    run_layer(wg2, 128, XSM_A1);
    write_act(sb2, XSM_A0);
    run_layer(wg3, 128, XSM_A0);

    // epilogue: g_eout[row*4+slot][col] = w * mish(C + b3)
#pragma unroll
    for (int mt = 0; mt < 2; mt++) {
#pragma unroll
        for (int half = 0; half < 2; half++) {
            int m = wm * 32 + mt * 16 + half * 8 + g;
            int gi = base + m;
            if (gi < cnt) {
                int packed = srow[m];
                int row = packed & 0xFFFF, slot = packed >> 16;
                float w = swt[m];
                float* dst = g_eout + ((size_t)(row * 4 + slot)) * HD;
#pragma unroll
                for (int nt = 0; nt < 4; nt++) {
                    int col = wn * 32 + nt * 8 + 2 * t;
                    float2 o;
                    o.x = w * mishf(c[mt][nt][half * 2 + 0] + sb3[col]);
                    o.y = w * mishf(c[mt][nt][half * 2 + 1] + sb3[col + 1]);
                    *(float2*)&dst[col] = o;
                }
            }
        }
    }
}

// ---------------- kernel 4: combine slots + final linear + epilogue ----------------
__global__ void __launch_bounds__(256, 1) final_kernel(
    const float* __restrict__ x, const float* __restrict__ fW,
    const float* __restrict__ fb, float* __restrict__ out)
{
    extern __shared__ float smem[];
    float* cs  = smem;             // 64*260
    float* fWs = cs + 64 * 260;    // 256*64
    int tid = threadIdx.x;
    int base = blockIdx.x * 64;

    for (int i = tid; i < 4096; i += 256)
        ((float4*)fWs)[i] = ((const float4*)fW)[i];
    for (int idx = tid; idx < 64 * 64; idx += 256) {
        int m = idx >> 6, n4 = (idx & 63) << 2;
        size_t rb = ((size_t)(base + m)) * 4 * HD + n4;
        float4 a = *(const float4*)&g_eout[rb];
        float4 b = *(const float4*)&g_eout[rb + 256];
        float4 c = *(const float4*)&g_eout[rb + 512];
        float4 d = *(const float4*)&g_eout[rb + 768];
        float4 v;
        v.x = a.x + b.x + c.x + d.x;
        v.y = a.y + b.y + c.y + d.y;
        v.z = a.z + b.z + c.z + d.z;
        v.w = a.w + b.w + c.w + d.w;
        *(float4*)&cs[m * 260 + n4] = v;
    }
    __syncthreads();

    int ty = tid >> 4, tx = tid & 15;
    float acc[4][4];
#pragma unroll
    for (int mi = 0; mi < 4; mi++)
#pragma unroll
        for (int ci = 0; ci < 4; ci++) acc[mi][ci] = 0.f;
#pragma unroll 4
    for (int k = 0; k < 256; k++) {
        float4 b = *(const float4*)&fWs[k * 64 + (tx << 2)];
#pragma unroll
        for (int mi = 0; mi < 4; mi++) {
            float a = cs[(ty * 4 + mi) * 260 + k];
            acc[mi][0] = fmaf(a, b.x, acc[mi][0]);
            acc[mi][1] = fmaf(a, b.y, acc[mi][1]);
            acc[mi][2] = fmaf(a, b.z, acc[mi][2]);
            acc[mi][3] = fmaf(a, b.w, acc[mi][3]);
        }
    }
#pragma unroll
    for (int mi = 0; mi < 4; mi++) {
        int row = base + ty * 4 + mi;
        float co = g_cout[row], ck = g_cskip[row];
        float4 xr = *(const float4*)&x[row * 64 + (tx << 2)];
        float4 o;
        o.x = fminf(fmaxf(co * (acc[mi][0] + __ldg(&fb[(tx << 2) + 0])) + ck * xr.x, -1.f), 1.f);
        o.y = fminf(fmaxf(co * (acc[mi][1] + __ldg(&fb[(tx << 2) + 1])) + ck * xr.y, -1.f), 1.f);
        o.z = fminf(fmaxf(co * (acc[mi][2] + __ldg(&fb[(tx << 2) + 2])) + ck * xr.z, -1.f), 1.f);
        o.w = fminf(fmaxf(co * (acc[mi][3] + __ldg(&fb[(tx << 2) + 3])) + ck * xr.w, -1.f), 1.f);
        *(float4*)&out[row * 64 + (tx << 2)] = o;
    }
}

// ---------------- kernel 5: aux loss ----------------
__global__ void aux_kernel(float* __restrict__ out, int out_size)
{
    if (threadIdx.x == 0 && out_size > NB * NACT) {
        float load[NE], mean = 0.f;
#pragma unroll
        for (int e = 0; e < NE; e++) { load[e] = (float)g_count[e] / (32768.0f + 1e-9f); mean += load[e]; }
        mean *= (1.0f / NE);
        float var = 0.f;
#pragma unroll
        for (int e = 0; e < NE; e++) { float d = load[e] - mean; var += d * d; }
        var *= (1.0f / (NE - 1));
        out[NB * NACT] = var + g_entropy / 32768.0f;
    }
}

extern "C" void kernel_launch(void* const* d_in, const int* in_sizes, int n_in,
                              void* d_out, int out_size)
{
    const float* x     = (const float*)d_in[0];
    const float* sigma = (const float*)d_in[1];
    const float* state = (const float*)d_in[2];
    const float* tW1 = (const float*)d_in[3];
    const float* tb1 = (const float*)d_in[4];
    const float* tW2 = (const float*)d_in[5];
    const float* tb2 = (const float*)d_in[6];
    const float* gW1 = (const float*)d_in[7];
    const float* gb1 = (const float*)d_in[8];
    const float* gW2 = (const float*)d_in[9];
    const float* gb2 = (const float*)d_in[10];
    const float* eW1 = (const float*)d_in[11];
    const float* eb1 = (const float*)d_in[12];
    const float* eW2 = (const float*)d_in[13];
    const float* eb2 = (const float*)d_in[14];
    const float* eW3 = (const float*)d_in[15];
    const float* eb3 = (const float*)d_in[16];
    const float* fW  = (const float*)d_in[17];
    const float* fb  = (const float*)d_in[18];
    float* out = (float*)d_out;

    const int gateSmem = (64 * 340 + 64 * 260 + 2 * 32 * 256 + 16) * 4;
    const int finSmem  = (64 * 260 + 256 * 64 + 16) * 4;
    cudaFuncSetAttribute(gate_kernel,   cudaFuncAttributeMaxDynamicSharedMemorySize, gateSmem);
    cudaFuncSetAttribute(expert_kernel, cudaFuncAttributeMaxDynamicSharedMemorySize, XSM_TOTAL);
    cudaFuncSetAttribute(final_kernel,  cudaFuncAttributeMaxDynamicSharedMemorySize, finSmem);

    prep_kernel<<<NB / 8, 256>>>(x, sigma, state, tW1, tb1, tW2, tb2);
    wconv_kernel<<<(NE * 168 * HD + 255) / 256, 256>>>(eW1, eW2, eW3);
    gate_kernel<<<NB / 64, 256, gateSmem>>>(gW1, gb1, gW2, gb2);
    expert_kernel<<<dim3(NB / 64, NE), 512, XSM_TOTAL>>>(eb1, eb2, eb3);
    final_kernel<<<NB / 64, 256, finSmem>>>(x, fW, fb, out);
    aux_kernel<<<1, 32>>>(out, out_size);
}